// round 10
// baseline (speedup 1.0000x reference)
#include <cuda_runtime.h>
#include <cuda_bf16.h>
#include <cuda_fp16.h>
#include <math.h>
#include <stdint.h>

#define N_ATOMS 10000
#define N_EDGES 250000
#define F_DIM   128
#define F3      384
#define N_RBF   20
#define CUTOFF  5.0f
#define EPSV    1e-8f
#define NTAB    8192
#define INV_STEP ((float)(NTAB - 1) / CUTOFF)
#define WT_PER_ITER 180224   // 16384+49152+32768+32768+49152

// ---------------- scratch (device globals; no allocation allowed) ----------------
__device__ __half2 g_tab2[(size_t)NTAB * F3];    // interleaved (W_k, W_{k+1}) lerp table
__device__ float4 g_geo [N_EDGES];               // (dir.x, dir.y, dir.z, d)
__device__ int    g_row [N_ATOMS + 1];           // CSR row pointers (idx_i is sorted)
__device__ float g_q   [N_ATOMS * F_DIM];
__device__ float g_mu  [N_ATOMS * 3 * F_DIM];
__device__ float g_h   [N_ATOMS * F_DIM];
__device__ float g_x   [N_ATOMS * F3];
__device__ __half2 g_pk[(size_t)N_ATOMS * F3];   // packed (x_p[t], mu_p[t]) gather source
__device__ float g_dmu [N_ATOMS * 3 * F_DIM];
__device__ float g_mumix[N_ATOMS * 3 * 2 * F_DIM];
__device__ float g_ctx [N_ATOMS * 2 * F_DIM];
__device__ float g_hm  [N_ATOMS * F_DIM];
__device__ float g_xm  [N_ATOMS * F3];
__device__ __nv_bfloat16 g_wH[3 * WT_PER_ITER];
__device__ __nv_bfloat16 g_wL[3 * WT_PER_ITER];

__device__ __forceinline__ void split_bf16(float v, __nv_bfloat16& h, __nv_bfloat16& l) {
    h = __float2bfloat16(v);
    l = __float2bfloat16(v - __bfloat162float(h));
}

#define MMA16816(d, a, b) \
    asm volatile("mma.sync.aligned.m16n8k16.row.col.f32.bf16.bf16.f32 " \
        "{%0,%1,%2,%3}, {%4,%5,%6,%7}, {%8,%9}, {%0,%1,%2,%3};" \
        : "+f"((d)[0]), "+f"((d)[1]), "+f"((d)[2]), "+f"((d)[3]) \
        : "r"((a)[0]), "r"((a)[1]), "r"((a)[2]), "r"((a)[3]), \
          "r"((b)[0]), "r"((b)[1]))

// ---------------- fused weight transpose + split for ALL 15 matrices ----------------
__global__ void transpose_all(const float* __restrict__ W1, const float* __restrict__ W2,
                              const float* __restrict__ Wmu, const float* __restrict__ M1,
                              const float* __restrict__ M2) {
    const int Ks[5]  = {128, 128, 128, 256, 128};
    const int Ns[5]  = {128, 384, 256, 128, 384};
    const int off[5] = {0, 16384, 65536, 98304, 131072};
    int m = blockIdx.y;
    int it = m / 5, s = m % 5;
    int K = Ks[s], N = Ns[s];
    int idx = blockIdx.x * blockDim.x + threadIdx.x;
    if (idx >= K * N) return;
    const float* src;
    switch (s) {
        case 0: src = W1  + (size_t)it * 16384; break;
        case 1: src = W2  + (size_t)it * 49152; break;
        case 2: src = Wmu + (size_t)it * 32768; break;
        case 3: src = M1  + (size_t)it * 32768; break;
        default: src = M2 + (size_t)it * 49152; break;
    }
    int k = idx / N, n = idx % N;
    size_t dst = (size_t)it * WT_PER_ITER + off[s] + (size_t)n * K + k;
    __nv_bfloat16 h, l;
    split_bf16(src[idx], h, l);
    g_wH[dst] = h;
    g_wL[dst] = l;
}

// ---------------- CSR row pointers ----------------
__global__ void build_rows(const int* __restrict__ idx_i) {
    int n = blockIdx.x * blockDim.x + threadIdx.x;
    if (n > N_ATOMS) return;
    int lo = 0, hi = N_EDGES;
    while (lo < hi) {
        int mid = (lo + hi) >> 1;
        if (idx_i[mid] < n) lo = mid + 1; else hi = mid;
    }
    g_row[n] = lo;
}

// ================= tensor-core GEMM via mma.sync (bf16x3 split) =================
__global__ __launch_bounds__(256)
void mma_gemm(const float* __restrict__ A,
              const __nv_bfloat16* __restrict__ BH,
              const __nv_bfloat16* __restrict__ BL,
              const float* __restrict__ bias, float* __restrict__ C,
              int M, int N, int K, int act) {
    __shared__ __nv_bfloat16 AsH[128][40], AsL[128][40];
    __shared__ __nv_bfloat16 BsH[64][40],  BsL[64][40];

    int tid = threadIdx.x, wid = tid >> 5, lane = tid & 31;
    int row0 = blockIdx.y * 128, col0 = blockIdx.x * 64;
    int wm = wid >> 1, wn = wid & 1;
    int gID = lane >> 2, tig = lane & 3;

    float acc[2][4][4];
    #pragma unroll
    for (int mt = 0; mt < 2; ++mt)
        #pragma unroll
        for (int nt = 0; nt < 4; ++nt)
            #pragma unroll
            for (int i = 0; i < 4; ++i) acc[mt][nt][i] = 0.f;

    int nc = K >> 5;
    float4 ra[4];
    uint4 rbh, rbl;
    int br = tid >> 2, bc = (tid & 3) * 8;

    #pragma unroll
    for (int p = 0; p < 4; ++p) {
        int r = (tid >> 3) + p * 32, cc = (tid & 7) * 4, gr = row0 + r;
        ra[p] = (gr < M) ? *(const float4*)&A[(size_t)gr * K + cc]
                         : make_float4(0.f, 0.f, 0.f, 0.f);
    }
    rbh = *(const uint4*)&BH[(size_t)(col0 + br) * K + bc];
    rbl = *(const uint4*)&BL[(size_t)(col0 + br) * K + bc];

    for (int c = 0; c < nc; ++c) {
        #pragma unroll
        for (int p = 0; p < 4; ++p) {
            int r = (tid >> 3) + p * 32, cc = (tid & 7) * 4;
            __nv_bfloat16 h, l;
            split_bf16(ra[p].x, h, l); AsH[r][cc+0] = h; AsL[r][cc+0] = l;
            split_bf16(ra[p].y, h, l); AsH[r][cc+1] = h; AsL[r][cc+1] = l;
            split_bf16(ra[p].z, h, l); AsH[r][cc+2] = h; AsL[r][cc+2] = l;
            split_bf16(ra[p].w, h, l); AsH[r][cc+3] = h; AsL[r][cc+3] = l;
        }
        *(uint4*)&BsH[br][bc] = rbh;
        *(uint4*)&BsL[br][bc] = rbl;
        __syncthreads();

        if (c + 1 < nc) {
            int k0n = (c + 1) << 5;
            #pragma unroll
            for (int p = 0; p < 4; ++p) {
                int r = (tid >> 3) + p * 32, cc = (tid & 7) * 4, gr = row0 + r;
                ra[p] = (gr < M) ? *(const float4*)&A[(size_t)gr * K + k0n + cc]
                                 : make_float4(0.f, 0.f, 0.f, 0.f);
            }
            rbh = *(const uint4*)&BH[(size_t)(col0 + br) * K + k0n + bc];
            rbl = *(const uint4*)&BL[(size_t)(col0 + br) * K + k0n + bc];
        }

        #pragma unroll
        for (int ks = 0; ks < 32; ks += 16) {
            uint32_t ah[2][4], al[2][4], bh[4][2], bl[4][2];
            int cc = ks + tig * 2;
            #pragma unroll
            for (int mt = 0; mt < 2; ++mt) {
                int r = wm * 32 + mt * 16 + gID;
                ah[mt][0] = *(const uint32_t*)&AsH[r][cc];
                ah[mt][1] = *(const uint32_t*)&AsH[r + 8][cc];
                ah[mt][2] = *(const uint32_t*)&AsH[r][cc + 8];
                ah[mt][3] = *(const uint32_t*)&AsH[r + 8][cc + 8];
                al[mt][0] = *(const uint32_t*)&AsL[r][cc];
                al[mt][1] = *(const uint32_t*)&AsL[r + 8][cc];
                al[mt][2] = *(const uint32_t*)&AsL[r][cc + 8];
                al[mt][3] = *(const uint32_t*)&AsL[r + 8][cc + 8];
            }
            #pragma unroll
            for (int nt = 0; nt < 4; ++nt) {
                int cr = wn * 32 + nt * 8 + gID;
                bh[nt][0] = *(const uint32_t*)&BsH[cr][cc];
                bh[nt][1] = *(const uint32_t*)&BsH[cr][cc + 8];
                bl[nt][0] = *(const uint32_t*)&BsL[cr][cc];
                bl[nt][1] = *(const uint32_t*)&BsL[cr][cc + 8];
            }
            #pragma unroll
            for (int mt = 0; mt < 2; ++mt)
                #pragma unroll
                for (int nt = 0; nt < 4; ++nt) {
                    MMA16816(acc[mt][nt], ah[mt], bh[nt]);
                    MMA16816(acc[mt][nt], ah[mt], bl[nt]);
                    MMA16816(acc[mt][nt], al[mt], bh[nt]);
                }
        }
        __syncthreads();
    }

    #pragma unroll
    for (int mt = 0; mt < 2; ++mt) {
        int r = row0 + wm * 32 + mt * 16 + gID;
        #pragma unroll
        for (int nt = 0; nt < 4; ++nt) {
            int c = col0 + wn * 32 + nt * 8 + tig * 2;
            float b0 = bias ? bias[c] : 0.f;
            float b1 = bias ? bias[c + 1] : 0.f;
            float v00 = acc[mt][nt][0] + b0, v01 = acc[mt][nt][1] + b1;
            float v10 = acc[mt][nt][2] + b0, v11 = acc[mt][nt][3] + b1;
            if (act) {
                v00 = v00 / (1.0f + expf(-v00));
                v01 = v01 / (1.0f + expf(-v01));
                v10 = v10 / (1.0f + expf(-v10));
                v11 = v11 / (1.0f + expf(-v11));
            }
            if (r < M)     { C[(size_t)r * N + c] = v00;       C[(size_t)r * N + c + 1] = v01; }
            if (r + 8 < M) { C[(size_t)(r + 8) * N + c] = v10; C[(size_t)(r + 8) * N + c + 1] = v11; }
        }
    }
}

// ================= PaiNN pipeline kernels =================
__global__ void edge_geom(const float* __restrict__ R,
                          const int* __restrict__ idx_i,
                          const int* __restrict__ idx_j,
                          const float* __restrict__ offs) {
    int e = blockIdx.x * blockDim.x + threadIdx.x;
    if (e >= N_EDGES) return;
    int i = idx_i[e], j = idx_j[e];
    float rx = R[j*3+0] - R[i*3+0] + offs[e*3+0];
    float ry = R[j*3+1] - R[i*3+1] + offs[e*3+1];
    float rz = R[j*3+2] - R[i*3+2] + offs[e*3+2];
    float d = sqrtf(rx*rx + ry*ry + rz*rz);
    float inv = 1.0f / d;
    g_geo[e] = make_float4(rx*inv, ry*inv, rz*inv, d);
}

__global__ void build_table(const float* __restrict__ filt_W,
                            const float* __restrict__ filt_b) {
    int k = blockIdx.x;
    int c = threadIdx.x;
    __shared__ float s_phi[2][N_RBF];
    const float step = CUTOFF / (float)(NTAB - 1);
    float d0 = (float)k * step;
    int k1 = (k + 1 < NTAB) ? k + 1 : k;
    float d1 = (float)k1 * step;
    if (c < N_RBF) {
        const float spacing = CUTOFF / (float)(N_RBF - 1);
        const float coeff = -0.5f / (spacing * spacing);
        float dd0 = d0 - (float)c * spacing;
        float dd1 = d1 - (float)c * spacing;
        s_phi[0][c] = expf(coeff * dd0 * dd0);
        s_phi[1][c] = expf(coeff * dd1 * dd1);
    }
    __syncthreads();
    float fc0 = (d0 < CUTOFF) ? 0.5f * (cosf(d0 * (float)(M_PI / 5.0)) + 1.0f) : 0.0f;
    float fc1 = (d1 < CUTOFF) ? 0.5f * (cosf(d1 * (float)(M_PI / 5.0)) + 1.0f) : 0.0f;
    float a0 = filt_b[c], a1 = filt_b[c];
    #pragma unroll
    for (int r = 0; r < N_RBF; ++r) {
        float w = filt_W[r * F3 + c];
        a0 += s_phi[0][r] * w;
        a1 += s_phi[1][r] * w;
    }
    g_tab2[(size_t)k * F3 + c] = __floats2half2_rn(a0 * fc0, a1 * fc1);
}

__global__ void init_atoms(const int* __restrict__ Z, const float* __restrict__ emb) {
    int n = blockIdx.x, t = threadIdx.x;
    int z = Z[n];
    g_q[n * F_DIM + t] = emb[z * F_DIM + t];
    #pragma unroll
    for (int a = 0; a < 3; ++a)
        g_mu[(n * 3 + a) * F_DIM + t] = 0.0f;
}

// ---------------- pack (x, mu) into interleaved half2 gather buffer ----------------
__global__ void pack_xm() {
    int n = blockIdx.x, t = threadIdx.x;   // 128 threads
    #pragma unroll
    for (int p = 0; p < 3; ++p) {
        float xv = g_x[(size_t)n * F3 + p * F_DIM + t];
        float mv = g_mu[(n * 3 + p) * F_DIM + t];
        g_pk[(size_t)n * F3 + p * F_DIM + t] = __floats2half2_rn(xv, mv);
    }
}

// ---------------- per-edge contribution (inlined) ----------------
__device__ __forceinline__ void edge_body(const int* __restrict__ idx_j, int e, int t,
                                          float& aq, float& a0, float& a1, float& a2) {
    float4 g = g_geo[e];
    float d = g.w;
    if (d >= CUTOFF) return;       // block-uniform branch
    int j = idx_j[e];

    float u = d * INV_STEP;
    int k = (int)u; if (k > NTAB - 2) k = NTAB - 2;
    float f = u - (float)k;
    const __half2* tp = &g_tab2[(size_t)k * F3];
    float2 p0 = __half22float2(tp[t]);
    float2 p1 = __half22float2(tp[F_DIM + t]);
    float2 p2 = __half22float2(tp[2 * F_DIM + t]);
    float w0 = fmaf(f, p0.y - p0.x, p0.x);
    float w1 = fmaf(f, p1.y - p1.x, p1.x);
    float w2 = fmaf(f, p2.y - p2.x, p2.x);

    const __half2* pk = &g_pk[(size_t)j * F3];
    float2 xm0 = __half22float2(pk[t]);                 // (x0, mu0)
    float2 xm1 = __half22float2(pk[F_DIM + t]);         // (x1, mu1)
    float2 xm2 = __half22float2(pk[2 * F_DIM + t]);     // (x2, mu2)

    aq += w0 * xm0.x;
    float dmuR  = w1 * xm1.x;
    float dmumu = w2 * xm2.x;
    a0 += dmuR * g.x + dmumu * xm0.y;
    a1 += dmuR * g.y + dmumu * xm1.y;
    a2 += dmuR * g.z + dmumu * xm2.y;
}

// ---------------- CSR edge message pass: one block per atom, unroll-2 ----------------
__global__ void edge_message_csr(const int* __restrict__ idx_j) {
    int n = blockIdx.x, t = threadIdx.x;   // 128 threads = F_DIM
    int e0 = g_row[n], e1 = g_row[n + 1];
    float aq0 = 0.f, x0 = 0.f, y0 = 0.f, z0 = 0.f;
    float aq1 = 0.f, x1 = 0.f, y1 = 0.f, z1 = 0.f;

    int e = e0;
    for (; e + 2 <= e1; e += 2) {
        edge_body(idx_j, e,     t, aq0, x0, y0, z0);
        edge_body(idx_j, e + 1, t, aq1, x1, y1, z1);
    }
    if (e < e1) edge_body(idx_j, e, t, aq0, x0, y0, z0);

    g_q[n * F_DIM + t] += aq0 + aq1;
    g_dmu[(n * 3 + 0) * F_DIM + t] = x0 + x1;
    g_dmu[(n * 3 + 1) * F_DIM + t] = y0 + y1;
    g_dmu[(n * 3 + 2) * F_DIM + t] = z0 + z1;
}

__global__ void apply_mu() {
    int n = blockIdx.x, t = threadIdx.x;
    #pragma unroll
    for (int a = 0; a < 3; ++a)
        g_mu[(n * 3 + a) * F_DIM + t] += g_dmu[(n * 3 + a) * F_DIM + t];
}

__global__ void ctx_kernel() {
    int n = blockIdx.x, t = threadIdx.x;
    float s = EPSV;
    #pragma unroll
    for (int a = 0; a < 3; ++a) {
        float v = g_mumix[(n * 3 + a) * (2 * F_DIM) + t];
        s += v * v;
    }
    g_ctx[n * 2 * F_DIM + t] = g_q[n * F_DIM + t];
    g_ctx[n * 2 * F_DIM + F_DIM + t] = sqrtf(s);
}

__global__ void mix_update() {
    int n = blockIdx.x, t = threadIdx.x;
    float dq   = g_xm[n * F3 + t];
    float dmu  = g_xm[n * F3 + F_DIM + t];
    float dqmu = g_xm[n * F3 + 2 * F_DIM + t];
    float s = 0.f;
    #pragma unroll
    for (int a = 0; a < 3; ++a) {
        float v = g_mumix[(n * 3 + a) * (2 * F_DIM) + t];
        float w = g_mumix[(n * 3 + a) * (2 * F_DIM) + F_DIM + t];
        s += v * w;
        g_mu[(n * 3 + a) * F_DIM + t] += dmu * w;
    }
    g_q[n * F_DIM + t] += dq + dqmu * s;
}

// ================= host launch =================
extern "C" void kernel_launch(void* const* d_in, const int* in_sizes, int n_in,
                              void* d_out, int out_size) {
    (void)in_sizes; (void)n_in; (void)out_size;
    const int*   Z       = (const int*)  d_in[0];
    const float* R       = (const float*)d_in[1];
    const int*   idx_i   = (const int*)  d_in[2];
    const int*   idx_j   = (const int*)  d_in[3];
    const float* offs    = (const float*)d_in[4];
    const float* emb     = (const float*)d_in[5];
    const float* filt_W  = (const float*)d_in[6];
    const float* filt_b  = (const float*)d_in[7];
    const float* int_W1  = (const float*)d_in[8];
    const float* int_b1  = (const float*)d_in[9];
    const float* int_W2  = (const float*)d_in[10];
    const float* int_b2  = (const float*)d_in[11];
    const float* mix_Wmu = (const float*)d_in[12];
    const float* mix_W1  = (const float*)d_in[13];
    const float* mix_b1  = (const float*)d_in[14];
    const float* mix_W2  = (const float*)d_in[15];
    const float* mix_b2  = (const float*)d_in[16];
    float* out = (float*)d_out;

    void *p_q, *p_mu, *p_h, *p_x, *p_mumix, *p_ctx, *p_hm, *p_xm, *p_wH, *p_wL;
    cudaGetSymbolAddress(&p_q, g_q);
    cudaGetSymbolAddress(&p_mu, g_mu);
    cudaGetSymbolAddress(&p_h, g_h);
    cudaGetSymbolAddress(&p_x, g_x);
    cudaGetSymbolAddress(&p_mumix, g_mumix);
    cudaGetSymbolAddress(&p_ctx, g_ctx);
    cudaGetSymbolAddress(&p_hm, g_hm);
    cudaGetSymbolAddress(&p_xm, g_xm);
    cudaGetSymbolAddress(&p_wH, g_wH);
    cudaGetSymbolAddress(&p_wL, g_wL);

    edge_geom<<<(N_EDGES + 255) / 256, 256>>>(R, idx_i, idx_j, offs);
    build_table<<<NTAB, F3>>>(filt_W, filt_b);
    init_atoms<<<N_ATOMS, 128>>>(Z, emb);
    transpose_all<<<dim3(192, 15), 256>>>(int_W1, int_W2, mix_Wmu, mix_W1, mix_W2);
    build_rows<<<(N_ATOMS + 256) / 256, 256>>>(idx_i);

    const __nv_bfloat16* wH = (const __nv_bfloat16*)p_wH;
    const __nv_bfloat16* wL = (const __nv_bfloat16*)p_wL;

    auto gemm = [&](const float* A, size_t woff, const float* bias, float* C,
                    int M, int N, int K, int act) {
        mma_gemm<<<dim3(N / 64, (M + 127) / 128), 256>>>(
            A, wH + woff, wL + woff, bias, C, M, N, K, act);
    };

    for (int it = 0; it < 3; ++it) {
        size_t wb = (size_t)it * WT_PER_ITER;
        gemm((const float*)p_q, wb + 0,
             int_b1 + (long)it * F_DIM, (float*)p_h, N_ATOMS, F_DIM, F_DIM, 1);
        gemm((const float*)p_h, wb + 16384,
             int_b2 + (long)it * F3, (float*)p_x, N_ATOMS, F3, F_DIM, 0);

        pack_xm<<<N_ATOMS, 128>>>();
        edge_message_csr<<<N_ATOMS, 128>>>(idx_j);
        apply_mu<<<N_ATOMS, 128>>>();

        gemm((const float*)p_mu, wb + 65536,
             nullptr, (float*)p_mumix, 3 * N_ATOMS, 2 * F_DIM, F_DIM, 0);
        ctx_kernel<<<N_ATOMS, 128>>>();
        gemm((const float*)p_ctx, wb + 98304,
             mix_b1 + (long)it * F_DIM, (float*)p_hm, N_ATOMS, F_DIM, 2 * F_DIM, 1);
        gemm((const float*)p_hm, wb + 131072,
             mix_b2 + (long)it * F3, (float*)p_xm, N_ATOMS, F3, F_DIM, 0);
        mix_update<<<N_ATOMS, 128>>>();
    }

    cudaMemcpyAsync(out, p_q, (size_t)N_ATOMS * F_DIM * sizeof(float),
                    cudaMemcpyDeviceToDevice);
    cudaMemcpyAsync(out + (size_t)N_ATOMS * F_DIM, p_mu,
                    (size_t)N_ATOMS * 3 * F_DIM * sizeof(float),
                    cudaMemcpyDeviceToDevice);
}

// round 11
// speedup vs baseline: 1.0255x; 1.0255x over previous
#include <cuda_runtime.h>
#include <cuda_bf16.h>
#include <cuda_fp16.h>
#include <math.h>
#include <stdint.h>

#define N_ATOMS 10000
#define N_EDGES 250000
#define F_DIM   128
#define F3      384
#define N_RBF   20
#define CUTOFF  5.0f
#define EPSV    1e-8f
#define NTAB    8192
#define INV_STEP ((float)(NTAB - 1) / CUTOFF)
#define WT_PER_ITER 180224   // 16384+49152+32768+32768+49152

// ---------------- scratch (device globals; no allocation allowed) ----------------
__device__ __half2 g_tab2[(size_t)NTAB * F3];    // interleaved (W_k, W_{k+1}) lerp table
__device__ float4 g_geo [N_EDGES];               // (dir.x, dir.y, dir.z, d)
__device__ int    g_row [N_ATOMS + 1];           // CSR row pointers (idx_i is sorted)
__device__ float g_q   [N_ATOMS * F_DIM];
__device__ float g_mu  [N_ATOMS * 3 * F_DIM];
__device__ float g_h   [N_ATOMS * F_DIM];
__device__ float g_x   [N_ATOMS * F3];
__device__ float g_dmu [N_ATOMS * 3 * F_DIM];
__device__ float g_mumix[N_ATOMS * 3 * 2 * F_DIM];
__device__ float g_ctx [N_ATOMS * 2 * F_DIM];
__device__ float g_hm  [N_ATOMS * F_DIM];
__device__ float g_xm  [N_ATOMS * F3];
__device__ __nv_bfloat16 g_wH[3 * WT_PER_ITER];
__device__ __nv_bfloat16 g_wL[3 * WT_PER_ITER];

__device__ __forceinline__ void split_bf16(float v, __nv_bfloat16& h, __nv_bfloat16& l) {
    h = __float2bfloat16(v);
    l = __float2bfloat16(v - __bfloat162float(h));
}

#define MMA16816(d, a, b) \
    asm volatile("mma.sync.aligned.m16n8k16.row.col.f32.bf16.bf16.f32 " \
        "{%0,%1,%2,%3}, {%4,%5,%6,%7}, {%8,%9}, {%0,%1,%2,%3};" \
        : "+f"((d)[0]), "+f"((d)[1]), "+f"((d)[2]), "+f"((d)[3]) \
        : "r"((a)[0]), "r"((a)[1]), "r"((a)[2]), "r"((a)[3]), \
          "r"((b)[0]), "r"((b)[1]))

// ================= fused precompute mega-kernel (grid-range dispatch) =================
// block ranges: [0,NTAB) table | [NTAB,+10000) init | next 2880 transpose |
//               next NB_GEO edge_geom | rest build_rows.   384 threads/block.
#define NB_GEO ((N_EDGES + 383) / 384)
#define NB_ROW ((N_ATOMS + 384) / 384)
#define NB_PRE (NTAB + N_ATOMS + 2880 + NB_GEO + NB_ROW)

__global__ __launch_bounds__(384)
void fused_pre(const float* __restrict__ R,
               const int* __restrict__ idx_i, const int* __restrict__ idx_j,
               const float* __restrict__ offs,
               const float* __restrict__ filt_W, const float* __restrict__ filt_b,
               const int* __restrict__ Z, const float* __restrict__ emb,
               const float* __restrict__ W1, const float* __restrict__ W2,
               const float* __restrict__ Wmu, const float* __restrict__ M1,
               const float* __restrict__ M2) {
    int b = blockIdx.x, t = threadIdx.x;

    if (b < NTAB) {
        // ---- build_table: interleaved (W_k, W_{k+1}) half2 ----
        int k = b, c = t;   // c in [0,384)
        __shared__ float s_phi[2][N_RBF];
        const float step = CUTOFF / (float)(NTAB - 1);
        float d0 = (float)k * step;
        int k1 = (k + 1 < NTAB) ? k + 1 : k;
        float d1 = (float)k1 * step;
        if (c < N_RBF) {
            const float spacing = CUTOFF / (float)(N_RBF - 1);
            const float coeff = -0.5f / (spacing * spacing);
            float dd0 = d0 - (float)c * spacing;
            float dd1 = d1 - (float)c * spacing;
            s_phi[0][c] = expf(coeff * dd0 * dd0);
            s_phi[1][c] = expf(coeff * dd1 * dd1);
        }
        __syncthreads();
        float fc0 = (d0 < CUTOFF) ? 0.5f * (cosf(d0 * (float)(M_PI / 5.0)) + 1.0f) : 0.0f;
        float fc1 = (d1 < CUTOFF) ? 0.5f * (cosf(d1 * (float)(M_PI / 5.0)) + 1.0f) : 0.0f;
        float a0 = filt_b[c], a1 = filt_b[c];
        #pragma unroll
        for (int r = 0; r < N_RBF; ++r) {
            float w = filt_W[r * F3 + c];
            a0 += s_phi[0][r] * w;
            a1 += s_phi[1][r] * w;
        }
        g_tab2[(size_t)k * F3 + c] = __floats2half2_rn(a0 * fc0, a1 * fc1);
        return;
    }
    b -= NTAB;

    if (b < N_ATOMS) {
        // ---- init_atoms ----
        if (t < F_DIM) {
            int z = Z[b];
            g_q[b * F_DIM + t] = emb[z * F_DIM + t];
            #pragma unroll
            for (int a = 0; a < 3; ++a)
                g_mu[(b * 3 + a) * F_DIM + t] = 0.0f;
        }
        return;
    }
    b -= N_ATOMS;

    if (b < 2880) {
        // ---- transpose_all (192 blocks x 256 threads per matrix) ----
        if (t >= 256) return;
        const int Ks[5]  = {128, 128, 128, 256, 128};
        const int Ns[5]  = {128, 384, 256, 128, 384};
        const int off[5] = {0, 16384, 65536, 98304, 131072};
        int m = b / 192;            // matrix id 0..14
        int local = b % 192;
        int it = m / 5, s = m % 5;
        int K = Ks[s], N = Ns[s];
        int idx = local * 256 + t;
        if (idx >= K * N) return;
        const float* src;
        switch (s) {
            case 0: src = W1  + (size_t)it * 16384; break;
            case 1: src = W2  + (size_t)it * 49152; break;
            case 2: src = Wmu + (size_t)it * 32768; break;
            case 3: src = M1  + (size_t)it * 32768; break;
            default: src = M2 + (size_t)it * 49152; break;
        }
        int k = idx / N, n = idx % N;
        size_t dst = (size_t)it * WT_PER_ITER + off[s] + (size_t)n * K + k;
        __nv_bfloat16 h, l;
        split_bf16(src[idx], h, l);
        g_wH[dst] = h;
        g_wL[dst] = l;
        return;
    }
    b -= 2880;

    if (b < NB_GEO) {
        // ---- edge_geom ----
        int e = b * 384 + t;
        if (e >= N_EDGES) return;
        int i = idx_i[e], j = idx_j[e];
        float rx = R[j*3+0] - R[i*3+0] + offs[e*3+0];
        float ry = R[j*3+1] - R[i*3+1] + offs[e*3+1];
        float rz = R[j*3+2] - R[i*3+2] + offs[e*3+2];
        float d = sqrtf(rx*rx + ry*ry + rz*rz);
        float inv = 1.0f / d;
        g_geo[e] = make_float4(rx*inv, ry*inv, rz*inv, d);
        return;
    }
    b -= NB_GEO;

    {
        // ---- build_rows ----
        int n = b * 384 + t;
        if (n > N_ATOMS) return;
        int lo = 0, hi = N_EDGES;
        while (lo < hi) {
            int mid = (lo + hi) >> 1;
            if (idx_i[mid] < n) lo = mid + 1; else hi = mid;
        }
        g_row[n] = lo;
    }
}

// ================= tensor-core GEMM via mma.sync (bf16x3 split) =================
__global__ __launch_bounds__(256)
void mma_gemm(const float* __restrict__ A,
              const __nv_bfloat16* __restrict__ BH,
              const __nv_bfloat16* __restrict__ BL,
              const float* __restrict__ bias, float* __restrict__ C,
              int M, int N, int K, int act) {
    __shared__ __nv_bfloat16 AsH[128][40], AsL[128][40];
    __shared__ __nv_bfloat16 BsH[64][40],  BsL[64][40];

    int tid = threadIdx.x, wid = tid >> 5, lane = tid & 31;
    int row0 = blockIdx.y * 128, col0 = blockIdx.x * 64;
    int wm = wid >> 1, wn = wid & 1;
    int gID = lane >> 2, tig = lane & 3;

    float acc[2][4][4];
    #pragma unroll
    for (int mt = 0; mt < 2; ++mt)
        #pragma unroll
        for (int nt = 0; nt < 4; ++nt)
            #pragma unroll
            for (int i = 0; i < 4; ++i) acc[mt][nt][i] = 0.f;

    int nc = K >> 5;
    float4 ra[4];
    uint4 rbh, rbl;
    int br = tid >> 2, bc = (tid & 3) * 8;

    #pragma unroll
    for (int p = 0; p < 4; ++p) {
        int r = (tid >> 3) + p * 32, cc = (tid & 7) * 4, gr = row0 + r;
        ra[p] = (gr < M) ? *(const float4*)&A[(size_t)gr * K + cc]
                         : make_float4(0.f, 0.f, 0.f, 0.f);
    }
    rbh = *(const uint4*)&BH[(size_t)(col0 + br) * K + bc];
    rbl = *(const uint4*)&BL[(size_t)(col0 + br) * K + bc];

    for (int c = 0; c < nc; ++c) {
        #pragma unroll
        for (int p = 0; p < 4; ++p) {
            int r = (tid >> 3) + p * 32, cc = (tid & 7) * 4;
            __nv_bfloat16 h, l;
            split_bf16(ra[p].x, h, l); AsH[r][cc+0] = h; AsL[r][cc+0] = l;
            split_bf16(ra[p].y, h, l); AsH[r][cc+1] = h; AsL[r][cc+1] = l;
            split_bf16(ra[p].z, h, l); AsH[r][cc+2] = h; AsL[r][cc+2] = l;
            split_bf16(ra[p].w, h, l); AsH[r][cc+3] = h; AsL[r][cc+3] = l;
        }
        *(uint4*)&BsH[br][bc] = rbh;
        *(uint4*)&BsL[br][bc] = rbl;
        __syncthreads();

        if (c + 1 < nc) {
            int k0n = (c + 1) << 5;
            #pragma unroll
            for (int p = 0; p < 4; ++p) {
                int r = (tid >> 3) + p * 32, cc = (tid & 7) * 4, gr = row0 + r;
                ra[p] = (gr < M) ? *(const float4*)&A[(size_t)gr * K + k0n + cc]
                                 : make_float4(0.f, 0.f, 0.f, 0.f);
            }
            rbh = *(const uint4*)&BH[(size_t)(col0 + br) * K + k0n + bc];
            rbl = *(const uint4*)&BL[(size_t)(col0 + br) * K + k0n + bc];
        }

        #pragma unroll
        for (int ks = 0; ks < 32; ks += 16) {
            uint32_t ah[2][4], al[2][4], bh[4][2], bl[4][2];
            int cc = ks + tig * 2;
            #pragma unroll
            for (int mt = 0; mt < 2; ++mt) {
                int r = wm * 32 + mt * 16 + gID;
                ah[mt][0] = *(const uint32_t*)&AsH[r][cc];
                ah[mt][1] = *(const uint32_t*)&AsH[r + 8][cc];
                ah[mt][2] = *(const uint32_t*)&AsH[r][cc + 8];
                ah[mt][3] = *(const uint32_t*)&AsH[r + 8][cc + 8];
                al[mt][0] = *(const uint32_t*)&AsL[r][cc];
                al[mt][1] = *(const uint32_t*)&AsL[r + 8][cc];
                al[mt][2] = *(const uint32_t*)&AsL[r][cc + 8];
                al[mt][3] = *(const uint32_t*)&AsL[r + 8][cc + 8];
            }
            #pragma unroll
            for (int nt = 0; nt < 4; ++nt) {
                int cr = wn * 32 + nt * 8 + gID;
                bh[nt][0] = *(const uint32_t*)&BsH[cr][cc];
                bh[nt][1] = *(const uint32_t*)&BsH[cr][cc + 8];
                bl[nt][0] = *(const uint32_t*)&BsL[cr][cc];
                bl[nt][1] = *(const uint32_t*)&BsL[cr][cc + 8];
            }
            #pragma unroll
            for (int mt = 0; mt < 2; ++mt)
                #pragma unroll
                for (int nt = 0; nt < 4; ++nt) {
                    MMA16816(acc[mt][nt], ah[mt], bh[nt]);
                    MMA16816(acc[mt][nt], ah[mt], bl[nt]);
                    MMA16816(acc[mt][nt], al[mt], bh[nt]);
                }
        }
        __syncthreads();
    }

    #pragma unroll
    for (int mt = 0; mt < 2; ++mt) {
        int r = row0 + wm * 32 + mt * 16 + gID;
        #pragma unroll
        for (int nt = 0; nt < 4; ++nt) {
            int c = col0 + wn * 32 + nt * 8 + tig * 2;
            float b0 = bias ? bias[c] : 0.f;
            float b1 = bias ? bias[c + 1] : 0.f;
            float v00 = acc[mt][nt][0] + b0, v01 = acc[mt][nt][1] + b1;
            float v10 = acc[mt][nt][2] + b0, v11 = acc[mt][nt][3] + b1;
            if (act) {
                v00 = v00 / (1.0f + expf(-v00));
                v01 = v01 / (1.0f + expf(-v01));
                v10 = v10 / (1.0f + expf(-v10));
                v11 = v11 / (1.0f + expf(-v11));
            }
            if (r < M)     { C[(size_t)r * N + c] = v00;       C[(size_t)r * N + c + 1] = v01; }
            if (r + 8 < M) { C[(size_t)(r + 8) * N + c] = v10; C[(size_t)(r + 8) * N + c + 1] = v11; }
        }
    }
}

// ---------------- per-edge contribution (inlined); fp32 gathers ----------------
__device__ __forceinline__ void edge_body(const int* __restrict__ idx_j, int e, int t,
                                          float& aq, float& a0, float& a1, float& a2) {
    float4 g = g_geo[e];
    float d = g.w;
    if (d >= CUTOFF) return;       // block-uniform branch
    int j = idx_j[e];

    float u = d * INV_STEP;
    int k = (int)u; if (k > NTAB - 2) k = NTAB - 2;
    float f = u - (float)k;
    const __half2* tp = &g_tab2[(size_t)k * F3];
    float2 p0 = __half22float2(tp[t]);
    float2 p1 = __half22float2(tp[F_DIM + t]);
    float2 p2 = __half22float2(tp[2 * F_DIM + t]);
    float w0 = fmaf(f, p0.y - p0.x, p0.x);
    float w1 = fmaf(f, p1.y - p1.x, p1.x);
    float w2 = fmaf(f, p2.y - p2.x, p2.x);

    const float* xr = &g_x[(size_t)j * F3];
    float xj0 = xr[t], xj1 = xr[F_DIM + t], xj2 = xr[2 * F_DIM + t];
    const float* mr = &g_mu[(size_t)j * 3 * F_DIM];
    float m0 = mr[t], m1 = mr[F_DIM + t], m2 = mr[2 * F_DIM + t];

    aq += w0 * xj0;
    float dmuR  = w1 * xj1;
    float dmumu = w2 * xj2;
    a0 += dmuR * g.x + dmumu * m0;
    a1 += dmuR * g.y + dmumu * m1;
    a2 += dmuR * g.z + dmumu * m2;
}

// ---------------- CSR edge message pass: one block per atom, unroll-4 ----------------
__global__ void edge_message_csr(const int* __restrict__ idx_j) {
    int n = blockIdx.x, t = threadIdx.x;   // 128 threads = F_DIM
    int e0 = g_row[n], e1 = g_row[n + 1];
    float aq0 = 0.f, x0 = 0.f, y0 = 0.f, z0 = 0.f;
    float aq1 = 0.f, x1 = 0.f, y1 = 0.f, z1 = 0.f;

    int e = e0;
    for (; e + 4 <= e1; e += 4) {
        edge_body(idx_j, e,     t, aq0, x0, y0, z0);
        edge_body(idx_j, e + 1, t, aq1, x1, y1, z1);
        edge_body(idx_j, e + 2, t, aq0, x0, y0, z0);
        edge_body(idx_j, e + 3, t, aq1, x1, y1, z1);
    }
    for (; e < e1; ++e) edge_body(idx_j, e, t, aq0, x0, y0, z0);

    g_q[n * F_DIM + t] += aq0 + aq1;
    g_dmu[(n * 3 + 0) * F_DIM + t] = x0 + x1;
    g_dmu[(n * 3 + 1) * F_DIM + t] = y0 + y1;
    g_dmu[(n * 3 + 2) * F_DIM + t] = z0 + z1;
}

__global__ void apply_mu() {
    int n = blockIdx.x, t = threadIdx.x;
    #pragma unroll
    for (int a = 0; a < 3; ++a)
        g_mu[(n * 3 + a) * F_DIM + t] += g_dmu[(n * 3 + a) * F_DIM + t];
}

__global__ void ctx_kernel() {
    int n = blockIdx.x, t = threadIdx.x;
    float s = EPSV;
    #pragma unroll
    for (int a = 0; a < 3; ++a) {
        float v = g_mumix[(n * 3 + a) * (2 * F_DIM) + t];
        s += v * v;
    }
    g_ctx[n * 2 * F_DIM + t] = g_q[n * F_DIM + t];
    g_ctx[n * 2 * F_DIM + F_DIM + t] = sqrtf(s);
}

__global__ void mix_update() {
    int n = blockIdx.x, t = threadIdx.x;
    float dq   = g_xm[n * F3 + t];
    float dmu  = g_xm[n * F3 + F_DIM + t];
    float dqmu = g_xm[n * F3 + 2 * F_DIM + t];
    float s = 0.f;
    #pragma unroll
    for (int a = 0; a < 3; ++a) {
        float v = g_mumix[(n * 3 + a) * (2 * F_DIM) + t];
        float w = g_mumix[(n * 3 + a) * (2 * F_DIM) + F_DIM + t];
        s += v * w;
        g_mu[(n * 3 + a) * F_DIM + t] += dmu * w;
    }
    g_q[n * F_DIM + t] += dq + dqmu * s;
}

// ================= host launch =================
extern "C" void kernel_launch(void* const* d_in, const int* in_sizes, int n_in,
                              void* d_out, int out_size) {
    (void)in_sizes; (void)n_in; (void)out_size;
    const int*   Z       = (const int*)  d_in[0];
    const float* R       = (const float*)d_in[1];
    const int*   idx_i   = (const int*)  d_in[2];
    const int*   idx_j   = (const int*)  d_in[3];
    const float* offs    = (const float*)d_in[4];
    const float* emb     = (const float*)d_in[5];
    const float* filt_W  = (const float*)d_in[6];
    const float* filt_b  = (const float*)d_in[7];
    const float* int_W1  = (const float*)d_in[8];
    const float* int_b1  = (const float*)d_in[9];
    const float* int_W2  = (const float*)d_in[10];
    const float* int_b2  = (const float*)d_in[11];
    const float* mix_Wmu = (const float*)d_in[12];
    const float* mix_W1  = (const float*)d_in[13];
    const float* mix_b1  = (const float*)d_in[14];
    const float* mix_W2  = (const float*)d_in[15];
    const float* mix_b2  = (const float*)d_in[16];
    float* out = (float*)d_out;

    void *p_q, *p_mu, *p_h, *p_x, *p_mumix, *p_ctx, *p_hm, *p_xm, *p_wH, *p_wL;
    cudaGetSymbolAddress(&p_q, g_q);
    cudaGetSymbolAddress(&p_mu, g_mu);
    cudaGetSymbolAddress(&p_h, g_h);
    cudaGetSymbolAddress(&p_x, g_x);
    cudaGetSymbolAddress(&p_mumix, g_mumix);
    cudaGetSymbolAddress(&p_ctx, g_ctx);
    cudaGetSymbolAddress(&p_hm, g_hm);
    cudaGetSymbolAddress(&p_xm, g_xm);
    cudaGetSymbolAddress(&p_wH, g_wH);
    cudaGetSymbolAddress(&p_wL, g_wL);

    // launch #1: everything loop-invariant, fused
    fused_pre<<<NB_PRE, 384>>>(R, idx_i, idx_j, offs, filt_W, filt_b, Z, emb,
                               int_W1, int_W2, mix_Wmu, mix_W1, mix_W2);

    const __nv_bfloat16* wH = (const __nv_bfloat16*)p_wH;
    const __nv_bfloat16* wL = (const __nv_bfloat16*)p_wL;

    auto gemm = [&](const float* A, size_t woff, const float* bias, float* C,
                    int M, int N, int K, int act) {
        mma_gemm<<<dim3(N / 64, (M + 127) / 128), 256>>>(
            A, wH + woff, wL + woff, bias, C, M, N, K, act);
    };

    for (int it = 0; it < 3; ++it) {
        size_t wb = (size_t)it * WT_PER_ITER;
        gemm((const float*)p_q, wb + 0,
             int_b1 + (long)it * F_DIM, (float*)p_h, N_ATOMS, F_DIM, F_DIM, 1);
        gemm((const float*)p_h, wb + 16384,
             int_b2 + (long)it * F3, (float*)p_x, N_ATOMS, F3, F_DIM, 0);

        edge_message_csr<<<N_ATOMS, 128>>>(idx_j);   // launch #4 on it==0 -> ncu window
        apply_mu<<<N_ATOMS, 128>>>();

        gemm((const float*)p_mu, wb + 65536,
             nullptr, (float*)p_mumix, 3 * N_ATOMS, 2 * F_DIM, F_DIM, 0);
        ctx_kernel<<<N_ATOMS, 128>>>();
        gemm((const float*)p_ctx, wb + 98304,
             mix_b1 + (long)it * F_DIM, (float*)p_hm, N_ATOMS, F_DIM, 2 * F_DIM, 1);
        gemm((const float*)p_hm, wb + 131072,
             mix_b2 + (long)it * F3, (float*)p_xm, N_ATOMS, F3, F_DIM, 0);
        mix_update<<<N_ATOMS, 128>>>();
    }

    cudaMemcpyAsync(out, p_q, (size_t)N_ATOMS * F_DIM * sizeof(float),
                    cudaMemcpyDeviceToDevice);
    cudaMemcpyAsync(out + (size_t)N_ATOMS * F_DIM, p_mu,
                    (size_t)N_ATOMS * 3 * F_DIM * sizeof(float),
                    cudaMemcpyDeviceToDevice);
}

// round 12
// speedup vs baseline: 1.0752x; 1.0484x over previous
#include <cuda_runtime.h>
#include <cuda_bf16.h>
#include <cuda_fp16.h>
#include <math.h>
#include <stdint.h>

#define N_ATOMS 10000
#define N_EDGES 250000
#define F_DIM   128
#define F3      384
#define N_RBF   20
#define CUTOFF  5.0f
#define EPSV    1e-8f
#define NTAB    8192
#define INV_STEP ((float)(NTAB - 1) / CUTOFF)
#define WT_PER_ITER 180224   // 16384+49152+32768+32768+49152

// ---------------- scratch (device globals; no allocation allowed) ----------------
__device__ __half2 g_tab2[(size_t)NTAB * F3];    // interleaved (W_k, W_{k+1}) lerp table
__device__ float4 g_geo [N_EDGES];               // (dir.x, dir.y, dir.z, d)
__device__ int    g_row [N_ATOMS + 1];           // CSR row pointers (idx_i is sorted)
__device__ float g_q   [N_ATOMS * F_DIM];
__device__ float g_mu  [N_ATOMS * 3 * F_DIM];
__device__ float g_h   [N_ATOMS * F_DIM];
__device__ float g_x   [N_ATOMS * F3];
__device__ float g_dmu [N_ATOMS * 3 * F_DIM];
__device__ float g_mumix[N_ATOMS * 3 * 2 * F_DIM];
__device__ float g_ctx [N_ATOMS * 2 * F_DIM];
__device__ float g_hm  [N_ATOMS * F_DIM];
__device__ float g_xm  [N_ATOMS * F3];
__device__ __half g_wF[3 * WT_PER_ITER];         // transposed fp16 weights [N,K]

__device__ __forceinline__ void split_f16(float v, __half& h, __half& l) {
    h = __float2half(v);
    l = __float2half(v - __half2float(h));
}

// fp16 MMA: D += A(16x16 f16, row) @ B(16x8 f16, col), f32 accum
#define MMA16816F(d, a, b) \
    asm volatile("mma.sync.aligned.m16n8k16.row.col.f32.f16.f16.f32 " \
        "{%0,%1,%2,%3}, {%4,%5,%6,%7}, {%8,%9}, {%0,%1,%2,%3};" \
        : "+f"((d)[0]), "+f"((d)[1]), "+f"((d)[2]), "+f"((d)[3]) \
        : "r"((a)[0]), "r"((a)[1]), "r"((a)[2]), "r"((a)[3]), \
          "r"((b)[0]), "r"((b)[1]))

// ================= fused precompute mega-kernel (grid-range dispatch) =================
#define NB_GEO ((N_EDGES + 383) / 384)
#define NB_ROW ((N_ATOMS + 384) / 384)
#define NB_PRE (NTAB + N_ATOMS + 2880 + NB_GEO + NB_ROW)

__global__ __launch_bounds__(384)
void fused_pre(const float* __restrict__ R,
               const int* __restrict__ idx_i, const int* __restrict__ idx_j,
               const float* __restrict__ offs,
               const float* __restrict__ filt_W, const float* __restrict__ filt_b,
               const int* __restrict__ Z, const float* __restrict__ emb,
               const float* __restrict__ W1, const float* __restrict__ W2,
               const float* __restrict__ Wmu, const float* __restrict__ M1,
               const float* __restrict__ M2) {
    int b = blockIdx.x, t = threadIdx.x;

    if (b < NTAB) {
        // ---- build_table: interleaved (W_k, W_{k+1}) half2 ----
        int k = b, c = t;
        __shared__ float s_phi[2][N_RBF];
        const float step = CUTOFF / (float)(NTAB - 1);
        float d0 = (float)k * step;
        int k1 = (k + 1 < NTAB) ? k + 1 : k;
        float d1 = (float)k1 * step;
        if (c < N_RBF) {
            const float spacing = CUTOFF / (float)(N_RBF - 1);
            const float coeff = -0.5f / (spacing * spacing);
            float dd0 = d0 - (float)c * spacing;
            float dd1 = d1 - (float)c * spacing;
            s_phi[0][c] = expf(coeff * dd0 * dd0);
            s_phi[1][c] = expf(coeff * dd1 * dd1);
        }
        __syncthreads();
        float fc0 = (d0 < CUTOFF) ? 0.5f * (cosf(d0 * (float)(M_PI / 5.0)) + 1.0f) : 0.0f;
        float fc1 = (d1 < CUTOFF) ? 0.5f * (cosf(d1 * (float)(M_PI / 5.0)) + 1.0f) : 0.0f;
        float a0 = filt_b[c], a1 = filt_b[c];
        #pragma unroll
        for (int r = 0; r < N_RBF; ++r) {
            float w = filt_W[r * F3 + c];
            a0 += s_phi[0][r] * w;
            a1 += s_phi[1][r] * w;
        }
        g_tab2[(size_t)k * F3 + c] = __floats2half2_rn(a0 * fc0, a1 * fc1);
        return;
    }
    b -= NTAB;

    if (b < N_ATOMS) {
        if (t < F_DIM) {
            int z = Z[b];
            g_q[b * F_DIM + t] = emb[z * F_DIM + t];
            #pragma unroll
            for (int a = 0; a < 3; ++a)
                g_mu[(b * 3 + a) * F_DIM + t] = 0.0f;
        }
        return;
    }
    b -= N_ATOMS;

    if (b < 2880) {
        // ---- transpose + fp16 convert (192 blocks x 256 threads per matrix) ----
        if (t >= 256) return;
        const int Ks[5]  = {128, 128, 128, 256, 128};
        const int Ns[5]  = {128, 384, 256, 128, 384};
        const int off[5] = {0, 16384, 65536, 98304, 131072};
        int m = b / 192;
        int local = b % 192;
        int it = m / 5, s = m % 5;
        int K = Ks[s], N = Ns[s];
        int idx = local * 256 + t;
        if (idx >= K * N) return;
        const float* src;
        switch (s) {
            case 0: src = W1  + (size_t)it * 16384; break;
            case 1: src = W2  + (size_t)it * 49152; break;
            case 2: src = Wmu + (size_t)it * 32768; break;
            case 3: src = M1  + (size_t)it * 32768; break;
            default: src = M2 + (size_t)it * 49152; break;
        }
        int k = idx / N, n = idx % N;
        g_wF[(size_t)it * WT_PER_ITER + off[s] + (size_t)n * K + k] = __float2half(src[idx]);
        return;
    }
    b -= 2880;

    if (b < NB_GEO) {
        int e = b * 384 + t;
        if (e >= N_EDGES) return;
        int i = idx_i[e], j = idx_j[e];
        float rx = R[j*3+0] - R[i*3+0] + offs[e*3+0];
        float ry = R[j*3+1] - R[i*3+1] + offs[e*3+1];
        float rz = R[j*3+2] - R[i*3+2] + offs[e*3+2];
        float d = sqrtf(rx*rx + ry*ry + rz*rz);
        float inv = 1.0f / d;
        g_geo[e] = make_float4(rx*inv, ry*inv, rz*inv, d);
        return;
    }
    b -= NB_GEO;

    {
        int n = b * 384 + t;
        if (n > N_ATOMS) return;
        int lo = 0, hi = N_EDGES;
        while (lo < hi) {
            int mid = (lo + hi) >> 1;
            if (idx_i[mid] < n) lo = mid + 1; else hi = mid;
        }
        g_row[n] = lo;
    }
}

// ================= tensor-core GEMM via mma.sync (fp16, A hi/lo = 2 MMAs) =================
__global__ __launch_bounds__(256)
void mma_gemm(const float* __restrict__ A,
              const __half* __restrict__ BF,
              const float* __restrict__ bias, float* __restrict__ C,
              int M, int N, int K, int act) {
    __shared__ __half AsH[128][40], AsL[128][40];
    __shared__ __half Bs[64][40];

    int tid = threadIdx.x, wid = tid >> 5, lane = tid & 31;
    int row0 = blockIdx.y * 128, col0 = blockIdx.x * 64;
    int wm = wid >> 1, wn = wid & 1;
    int gID = lane >> 2, tig = lane & 3;

    float acc[2][4][4];
    #pragma unroll
    for (int mt = 0; mt < 2; ++mt)
        #pragma unroll
        for (int nt = 0; nt < 4; ++nt)
            #pragma unroll
            for (int i = 0; i < 4; ++i) acc[mt][nt][i] = 0.f;

    int nc = K >> 5;
    float4 ra[4];
    uint4 rb;
    int br = tid >> 2, bc = (tid & 3) * 8;

    #pragma unroll
    for (int p = 0; p < 4; ++p) {
        int r = (tid >> 3) + p * 32, cc = (tid & 7) * 4, gr = row0 + r;
        ra[p] = (gr < M) ? *(const float4*)&A[(size_t)gr * K + cc]
                         : make_float4(0.f, 0.f, 0.f, 0.f);
    }
    rb = *(const uint4*)&BF[(size_t)(col0 + br) * K + bc];

    for (int c = 0; c < nc; ++c) {
        #pragma unroll
        for (int p = 0; p < 4; ++p) {
            int r = (tid >> 3) + p * 32, cc = (tid & 7) * 4;
            __half h, l;
            split_f16(ra[p].x, h, l); AsH[r][cc+0] = h; AsL[r][cc+0] = l;
            split_f16(ra[p].y, h, l); AsH[r][cc+1] = h; AsL[r][cc+1] = l;
            split_f16(ra[p].z, h, l); AsH[r][cc+2] = h; AsL[r][cc+2] = l;
            split_f16(ra[p].w, h, l); AsH[r][cc+3] = h; AsL[r][cc+3] = l;
        }
        *(uint4*)&Bs[br][bc] = rb;
        __syncthreads();

        if (c + 1 < nc) {
            int k0n = (c + 1) << 5;
            #pragma unroll
            for (int p = 0; p < 4; ++p) {
                int r = (tid >> 3) + p * 32, cc = (tid & 7) * 4, gr = row0 + r;
                ra[p] = (gr < M) ? *(const float4*)&A[(size_t)gr * K + k0n + cc]
                                 : make_float4(0.f, 0.f, 0.f, 0.f);
            }
            rb = *(const uint4*)&BF[(size_t)(col0 + br) * K + k0n + bc];
        }

        #pragma unroll
        for (int ks = 0; ks < 32; ks += 16) {
            uint32_t ah[2][4], al[2][4], bf[4][2];
            int cc = ks + tig * 2;
            #pragma unroll
            for (int mt = 0; mt < 2; ++mt) {
                int r = wm * 32 + mt * 16 + gID;
                ah[mt][0] = *(const uint32_t*)&AsH[r][cc];
                ah[mt][1] = *(const uint32_t*)&AsH[r + 8][cc];
                ah[mt][2] = *(const uint32_t*)&AsH[r][cc + 8];
                ah[mt][3] = *(const uint32_t*)&AsH[r + 8][cc + 8];
                al[mt][0] = *(const uint32_t*)&AsL[r][cc];
                al[mt][1] = *(const uint32_t*)&AsL[r + 8][cc];
                al[mt][2] = *(const uint32_t*)&AsL[r][cc + 8];
                al[mt][3] = *(const uint32_t*)&AsL[r + 8][cc + 8];
            }
            #pragma unroll
            for (int nt = 0; nt < 4; ++nt) {
                int cr = wn * 32 + nt * 8 + gID;
                bf[nt][0] = *(const uint32_t*)&Bs[cr][cc];
                bf[nt][1] = *(const uint32_t*)&Bs[cr][cc + 8];
            }
            #pragma unroll
            for (int mt = 0; mt < 2; ++mt)
                #pragma unroll
                for (int nt = 0; nt < 4; ++nt) {
                    MMA16816F(acc[mt][nt], ah[mt], bf[nt]);
                    MMA16816F(acc[mt][nt], al[mt], bf[nt]);
                }
        }
        __syncthreads();
    }

    #pragma unroll
    for (int mt = 0; mt < 2; ++mt) {
        int r = row0 + wm * 32 + mt * 16 + gID;
        #pragma unroll
        for (int nt = 0; nt < 4; ++nt) {
            int c = col0 + wn * 32 + nt * 8 + tig * 2;
            float b0 = bias ? bias[c] : 0.f;
            float b1 = bias ? bias[c + 1] : 0.f;
            float v00 = acc[mt][nt][0] + b0, v01 = acc[mt][nt][1] + b1;
            float v10 = acc[mt][nt][2] + b0, v11 = acc[mt][nt][3] + b1;
            if (act) {
                v00 = v00 / (1.0f + expf(-v00));
                v01 = v01 / (1.0f + expf(-v01));
                v10 = v10 / (1.0f + expf(-v10));
                v11 = v11 / (1.0f + expf(-v11));
            }
            if (r < M)     { C[(size_t)r * N + c] = v00;       C[(size_t)r * N + c + 1] = v01; }
            if (r + 8 < M) { C[(size_t)(r + 8) * N + c] = v10; C[(size_t)(r + 8) * N + c + 1] = v11; }
        }
    }
}

// ---------------- per-edge contribution (inlined); fp32 gathers ----------------
__device__ __forceinline__ void edge_body(const int* __restrict__ idx_j, int e, int t,
                                          float& aq, float& a0, float& a1, float& a2) {
    float4 g = g_geo[e];
    float d = g.w;
    if (d >= CUTOFF) return;
    int j = idx_j[e];

    float u = d * INV_STEP;
    int k = (int)u; if (k > NTAB - 2) k = NTAB - 2;
    float f = u - (float)k;
    const __half2* tp = &g_tab2[(size_t)k * F3];
    float2 p0 = __half22float2(tp[t]);
    float2 p1 = __half22float2(tp[F_DIM + t]);
    float2 p2 = __half22float2(tp[2 * F_DIM + t]);
    float w0 = fmaf(f, p0.y - p0.x, p0.x);
    float w1 = fmaf(f, p1.y - p1.x, p1.x);
    float w2 = fmaf(f, p2.y - p2.x, p2.x);

    const float* xr = &g_x[(size_t)j * F3];
    float xj0 = xr[t], xj1 = xr[F_DIM + t], xj2 = xr[2 * F_DIM + t];
    const float* mr = &g_mu[(size_t)j * 3 * F_DIM];
    float m0 = mr[t], m1 = mr[F_DIM + t], m2 = mr[2 * F_DIM + t];

    aq += w0 * xj0;
    float dmuR  = w1 * xj1;
    float dmumu = w2 * xj2;
    a0 += dmuR * g.x + dmumu * m0;
    a1 += dmuR * g.y + dmumu * m1;
    a2 += dmuR * g.z + dmumu * m2;
}

// ---------------- CSR edge message pass: one block per atom, unroll-4 ----------------
__global__ void edge_message_csr(const int* __restrict__ idx_j) {
    int n = blockIdx.x, t = threadIdx.x;
    int e0 = g_row[n], e1 = g_row[n + 1];
    float aq0 = 0.f, x0 = 0.f, y0 = 0.f, z0 = 0.f;
    float aq1 = 0.f, x1 = 0.f, y1 = 0.f, z1 = 0.f;

    int e = e0;
    for (; e + 4 <= e1; e += 4) {
        edge_body(idx_j, e,     t, aq0, x0, y0, z0);
        edge_body(idx_j, e + 1, t, aq1, x1, y1, z1);
        edge_body(idx_j, e + 2, t, aq0, x0, y0, z0);
        edge_body(idx_j, e + 3, t, aq1, x1, y1, z1);
    }
    for (; e < e1; ++e) edge_body(idx_j, e, t, aq0, x0, y0, z0);

    g_q[n * F_DIM + t] += aq0 + aq1;
    g_dmu[(n * 3 + 0) * F_DIM + t] = x0 + x1;
    g_dmu[(n * 3 + 1) * F_DIM + t] = y0 + y1;
    g_dmu[(n * 3 + 2) * F_DIM + t] = z0 + z1;
}

__global__ void apply_mu() {
    int n = blockIdx.x, t = threadIdx.x;
    #pragma unroll
    for (int a = 0; a < 3; ++a)
        g_mu[(n * 3 + a) * F_DIM + t] += g_dmu[(n * 3 + a) * F_DIM + t];
}

__global__ void ctx_kernel() {
    int n = blockIdx.x, t = threadIdx.x;
    float s = EPSV;
    #pragma unroll
    for (int a = 0; a < 3; ++a) {
        float v = g_mumix[(n * 3 + a) * (2 * F_DIM) + t];
        s += v * v;
    }
    g_ctx[n * 2 * F_DIM + t] = g_q[n * F_DIM + t];
    g_ctx[n * 2 * F_DIM + F_DIM + t] = sqrtf(s);
}

__global__ void mix_update() {
    int n = blockIdx.x, t = threadIdx.x;
    float dq   = g_xm[n * F3 + t];
    float dmu  = g_xm[n * F3 + F_DIM + t];
    float dqmu = g_xm[n * F3 + 2 * F_DIM + t];
    float s = 0.f;
    #pragma unroll
    for (int a = 0; a < 3; ++a) {
        float v = g_mumix[(n * 3 + a) * (2 * F_DIM) + t];
        float w = g_mumix[(n * 3 + a) * (2 * F_DIM) + F_DIM + t];
        s += v * w;
        g_mu[(n * 3 + a) * F_DIM + t] += dmu * w;
    }
    g_q[n * F_DIM + t] += dq + dqmu * s;
}

// ================= host launch =================
extern "C" void kernel_launch(void* const* d_in, const int* in_sizes, int n_in,
                              void* d_out, int out_size) {
    (void)in_sizes; (void)n_in; (void)out_size;
    const int*   Z       = (const int*)  d_in[0];
    const float* R       = (const float*)d_in[1];
    const int*   idx_i   = (const int*)  d_in[2];
    const int*   idx_j   = (const int*)  d_in[3];
    const float* offs    = (const float*)d_in[4];
    const float* emb     = (const float*)d_in[5];
    const float* filt_W  = (const float*)d_in[6];
    const float* filt_b  = (const float*)d_in[7];
    const float* int_W1  = (const float*)d_in[8];
    const float* int_b1  = (const float*)d_in[9];
    const float* int_W2  = (const float*)d_in[10];
    const float* int_b2  = (const float*)d_in[11];
    const float* mix_Wmu = (const float*)d_in[12];
    const float* mix_W1  = (const float*)d_in[13];
    const float* mix_b1  = (const float*)d_in[14];
    const float* mix_W2  = (const float*)d_in[15];
    const float* mix_b2  = (const float*)d_in[16];
    float* out = (float*)d_out;

    void *p_q, *p_mu, *p_h, *p_x, *p_mumix, *p_ctx, *p_hm, *p_xm, *p_wF;
    cudaGetSymbolAddress(&p_q, g_q);
    cudaGetSymbolAddress(&p_mu, g_mu);
    cudaGetSymbolAddress(&p_h, g_h);
    cudaGetSymbolAddress(&p_x, g_x);
    cudaGetSymbolAddress(&p_mumix, g_mumix);
    cudaGetSymbolAddress(&p_ctx, g_ctx);
    cudaGetSymbolAddress(&p_hm, g_hm);
    cudaGetSymbolAddress(&p_xm, g_xm);
    cudaGetSymbolAddress(&p_wF, g_wF);

    fused_pre<<<NB_PRE, 384>>>(R, idx_i, idx_j, offs, filt_W, filt_b, Z, emb,
                               int_W1, int_W2, mix_Wmu, mix_W1, mix_W2);

    const __half* wF = (const __half*)p_wF;

    auto gemm = [&](const float* A, size_t woff, const float* bias, float* C,
                    int M, int N, int K, int act) {
        mma_gemm<<<dim3(N / 64, (M + 127) / 128), 256>>>(
            A, wF + woff, bias, C, M, N, K, act);
    };

    for (int it = 0; it < 3; ++it) {
        size_t wb = (size_t)it * WT_PER_ITER;
        gemm((const float*)p_q, wb + 0,
             int_b1 + (long)it * F_DIM, (float*)p_h, N_ATOMS, F_DIM, F_DIM, 1);
        gemm((const float*)p_h, wb + 16384,
             int_b2 + (long)it * F3, (float*)p_x, N_ATOMS, F3, F_DIM, 0);

        edge_message_csr<<<N_ATOMS, 128>>>(idx_j);
        apply_mu<<<N_ATOMS, 128>>>();

        gemm((const float*)p_mu, wb + 65536,
             nullptr, (float*)p_mumix, 3 * N_ATOMS, 2 * F_DIM, F_DIM, 0);
        ctx_kernel<<<N_ATOMS, 128>>>();
        gemm((const float*)p_ctx, wb + 98304,
             mix_b1 + (long)it * F_DIM, (float*)p_hm, N_ATOMS, F_DIM, 2 * F_DIM, 1);
        gemm((const float*)p_hm, wb + 131072,
             mix_b2 + (long)it * F3, (float*)p_xm, N_ATOMS, F3, F_DIM, 0);
        mix_update<<<N_ATOMS, 128>>>();
    }

    cudaMemcpyAsync(out, p_q, (size_t)N_ATOMS * F_DIM * sizeof(float),
                    cudaMemcpyDeviceToDevice);
    cudaMemcpyAsync(out + (size_t)N_ATOMS * F_DIM, p_mu,
                    (size_t)N_ATOMS * 3 * F_DIM * sizeof(float),
                    cudaMemcpyDeviceToDevice);
}

// round 13
// speedup vs baseline: 1.1659x; 1.0843x over previous
#include <cuda_runtime.h>
#include <cuda_bf16.h>
#include <cuda_fp16.h>
#include <math.h>
#include <stdint.h>

#define N_ATOMS 10000
#define N_EDGES 250000
#define F_DIM   128
#define F3      384
#define N_RBF   20
#define CUTOFF  5.0f
#define EPSV    1e-8f
#define NTAB    8192
#define INV_STEP ((float)(NTAB - 1) / CUTOFF)
#define WT_PER_ITER 180224   // 16384+49152+32768+32768+49152

// ---------------- scratch (device globals; no allocation allowed) ----------------
__device__ __half2 g_tab2[(size_t)NTAB * F3];    // interleaved (W_k, W_{k+1}) lerp table
__device__ float4 g_geo [N_EDGES];               // (dir.x, dir.y, dir.z, d)
__device__ int    g_row [N_ATOMS + 1];           // CSR row pointers (idx_i is sorted)
__device__ float g_q   [N_ATOMS * F_DIM];
__device__ float g_mu  [N_ATOMS * 3 * F_DIM];
__device__ float g_h   [N_ATOMS * F_DIM];
__device__ float g_x   [N_ATOMS * F3];
__device__ float g_dmu [N_ATOMS * 3 * F_DIM];
__device__ float g_mumix[N_ATOMS * 3 * 2 * F_DIM];
__device__ float g_hm  [N_ATOMS * F_DIM];
__device__ float g_xm  [N_ATOMS * F3];
__device__ __half g_wF[3 * WT_PER_ITER];         // transposed fp16 weights [N,K]

__device__ __forceinline__ void split_f16(float v, __half& h, __half& l) {
    h = __float2half(v);
    l = __float2half(v - __half2float(h));
}

// fp16 MMA: D += A(16x16 f16, row) @ B(16x8 f16, col), f32 accum
#define MMA16816F(d, a, b) \
    asm volatile("mma.sync.aligned.m16n8k16.row.col.f32.f16.f16.f32 " \
        "{%0,%1,%2,%3}, {%4,%5,%6,%7}, {%8,%9}, {%0,%1,%2,%3};" \
        : "+f"((d)[0]), "+f"((d)[1]), "+f"((d)[2]), "+f"((d)[3]) \
        : "r"((a)[0]), "r"((a)[1]), "r"((a)[2]), "r"((a)[3]), \
          "r"((b)[0]), "r"((b)[1]))

// ================= fused precompute mega-kernel (grid-range dispatch) =================
#define NB_GEO ((N_EDGES + 383) / 384)
#define NB_ROW ((N_ATOMS + 384) / 384)
#define NB_PRE (NTAB + N_ATOMS + 2880 + NB_GEO + NB_ROW)

__global__ __launch_bounds__(384)
void fused_pre(const float* __restrict__ R,
               const int* __restrict__ idx_i, const int* __restrict__ idx_j,
               const float* __restrict__ offs,
               const float* __restrict__ filt_W, const float* __restrict__ filt_b,
               const int* __restrict__ Z, const float* __restrict__ emb,
               const float* __restrict__ W1, const float* __restrict__ W2,
               const float* __restrict__ Wmu, const float* __restrict__ M1,
               const float* __restrict__ M2) {
    int b = blockIdx.x, t = threadIdx.x;

    if (b < NTAB) {
        int k = b, c = t;
        __shared__ float s_phi[2][N_RBF];
        const float step = CUTOFF / (float)(NTAB - 1);
        float d0 = (float)k * step;
        int k1 = (k + 1 < NTAB) ? k + 1 : k;
        float d1 = (float)k1 * step;
        if (c < N_RBF) {
            const float spacing = CUTOFF / (float)(N_RBF - 1);
            const float coeff = -0.5f / (spacing * spacing);
            float dd0 = d0 - (float)c * spacing;
            float dd1 = d1 - (float)c * spacing;
            s_phi[0][c] = expf(coeff * dd0 * dd0);
            s_phi[1][c] = expf(coeff * dd1 * dd1);
        }
        __syncthreads();
        float fc0 = (d0 < CUTOFF) ? 0.5f * (cosf(d0 * (float)(M_PI / 5.0)) + 1.0f) : 0.0f;
        float fc1 = (d1 < CUTOFF) ? 0.5f * (cosf(d1 * (float)(M_PI / 5.0)) + 1.0f) : 0.0f;
        float a0 = filt_b[c], a1 = filt_b[c];
        #pragma unroll
        for (int r = 0; r < N_RBF; ++r) {
            float w = filt_W[r * F3 + c];
            a0 += s_phi[0][r] * w;
            a1 += s_phi[1][r] * w;
        }
        g_tab2[(size_t)k * F3 + c] = __floats2half2_rn(a0 * fc0, a1 * fc1);
        return;
    }
    b -= NTAB;

    if (b < N_ATOMS) {
        if (t < F_DIM) {
            int z = Z[b];
            g_q[b * F_DIM + t] = emb[z * F_DIM + t];
            #pragma unroll
            for (int a = 0; a < 3; ++a)
                g_mu[(b * 3 + a) * F_DIM + t] = 0.0f;
        }
        return;
    }
    b -= N_ATOMS;

    if (b < 2880) {
        if (t >= 256) return;
        const int Ks[5]  = {128, 128, 128, 256, 128};
        const int Ns[5]  = {128, 384, 256, 128, 384};
        const int off[5] = {0, 16384, 65536, 98304, 131072};
        int m = b / 192;
        int local = b % 192;
        int it = m / 5, s = m % 5;
        int K = Ks[s], N = Ns[s];
        int idx = local * 256 + t;
        if (idx >= K * N) return;
        const float* src;
        switch (s) {
            case 0: src = W1  + (size_t)it * 16384; break;
            case 1: src = W2  + (size_t)it * 49152; break;
            case 2: src = Wmu + (size_t)it * 32768; break;
            case 3: src = M1  + (size_t)it * 32768; break;
            default: src = M2 + (size_t)it * 49152; break;
        }
        int k = idx / N, n = idx % N;
        g_wF[(size_t)it * WT_PER_ITER + off[s] + (size_t)n * K + k] = __float2half(src[idx]);
        return;
    }
    b -= 2880;

    if (b < NB_GEO) {
        int e = b * 384 + t;
        if (e >= N_EDGES) return;
        int i = idx_i[e], j = idx_j[e];
        float rx = R[j*3+0] - R[i*3+0] + offs[e*3+0];
        float ry = R[j*3+1] - R[i*3+1] + offs[e*3+1];
        float rz = R[j*3+2] - R[i*3+2] + offs[e*3+2];
        float d = sqrtf(rx*rx + ry*ry + rz*rz);
        float inv = 1.0f / d;
        g_geo[e] = make_float4(rx*inv, ry*inv, rz*inv, d);
        return;
    }
    b -= NB_GEO;

    {
        int n = b * 384 + t;
        if (n > N_ATOMS) return;
        int lo = 0, hi = N_EDGES;
        while (lo < hi) {
            int mid = (lo + hi) >> 1;
            if (idx_i[mid] < n) lo = mid + 1; else hi = mid;
        }
        g_row[n] = lo;
    }
}

// ================= A-tile loader (compile-time MODE) =================
// MODE 0: A[gr*K + k]
// MODE 1: A[gr*K + k] + A2[gr*K + k]                 (mu + dmu)
// MODE 2: k<128 -> A(q)[gr*128 + k]; else ||mu_V|| from A2(mumix)[(gr*3+a)*256 + k-128]
template<int MODE>
__device__ __forceinline__ float4 load_a(const float* __restrict__ A,
                                         const float* __restrict__ A2,
                                         int gr, int M, int K, int kcol) {
    if (gr >= M) return make_float4(0.f, 0.f, 0.f, 0.f);
    if (MODE == 0) {
        return *(const float4*)&A[(size_t)gr * K + kcol];
    } else if (MODE == 1) {
        float4 a = *(const float4*)&A[(size_t)gr * K + kcol];
        float4 b = *(const float4*)&A2[(size_t)gr * K + kcol];
        return make_float4(a.x + b.x, a.y + b.y, a.z + b.z, a.w + b.w);
    } else {
        if (kcol < 128) return *(const float4*)&A[(size_t)gr * 128 + kcol];
        int c = kcol - 128;
        float4 v0 = *(const float4*)&A2[((size_t)gr * 3 + 0) * 256 + c];
        float4 v1 = *(const float4*)&A2[((size_t)gr * 3 + 1) * 256 + c];
        float4 v2 = *(const float4*)&A2[((size_t)gr * 3 + 2) * 256 + c];
        return make_float4(
            sqrtf(EPSV + v0.x*v0.x + v1.x*v1.x + v2.x*v2.x),
            sqrtf(EPSV + v0.y*v0.y + v1.y*v1.y + v2.y*v2.y),
            sqrtf(EPSV + v0.z*v0.z + v1.z*v1.z + v2.z*v2.z),
            sqrtf(EPSV + v0.w*v0.w + v1.w*v1.w + v2.w*v2.w));
    }
}

// ================= tensor-core GEMM via mma.sync (fp16, A hi/lo = 2 MMAs) =================
template<int MODE>
__global__ __launch_bounds__(256)
void mma_gemm(const float* __restrict__ A, const float* __restrict__ A2,
              const __half* __restrict__ BF,
              const float* __restrict__ bias, float* __restrict__ C,
              int M, int N, int K, int act) {
    __shared__ __half AsH[128][40], AsL[128][40];
    __shared__ __half Bs[64][40];

    int tid = threadIdx.x, wid = tid >> 5, lane = tid & 31;
    int row0 = blockIdx.y * 128, col0 = blockIdx.x * 64;
    int wm = wid >> 1, wn = wid & 1;
    int gID = lane >> 2, tig = lane & 3;

    float acc[2][4][4];
    #pragma unroll
    for (int mt = 0; mt < 2; ++mt)
        #pragma unroll
        for (int nt = 0; nt < 4; ++nt)
            #pragma unroll
            for (int i = 0; i < 4; ++i) acc[mt][nt][i] = 0.f;

    int nc = K >> 5;
    float4 ra[4];
    uint4 rb;
    int br = tid >> 2, bc = (tid & 3) * 8;
    int arf = tid >> 3, acf = (tid & 7) * 4;

    #pragma unroll
    for (int p = 0; p < 4; ++p)
        ra[p] = load_a<MODE>(A, A2, row0 + arf + p * 32, M, K, acf);
    rb = *(const uint4*)&BF[(size_t)(col0 + br) * K + bc];

    for (int c = 0; c < nc; ++c) {
        #pragma unroll
        for (int p = 0; p < 4; ++p) {
            int r = arf + p * 32;
            __half h, l;
            split_f16(ra[p].x, h, l); AsH[r][acf+0] = h; AsL[r][acf+0] = l;
            split_f16(ra[p].y, h, l); AsH[r][acf+1] = h; AsL[r][acf+1] = l;
            split_f16(ra[p].z, h, l); AsH[r][acf+2] = h; AsL[r][acf+2] = l;
            split_f16(ra[p].w, h, l); AsH[r][acf+3] = h; AsL[r][acf+3] = l;
        }
        *(uint4*)&Bs[br][bc] = rb;
        __syncthreads();

        if (c + 1 < nc) {
            int k0n = (c + 1) << 5;
            #pragma unroll
            for (int p = 0; p < 4; ++p)
                ra[p] = load_a<MODE>(A, A2, row0 + arf + p * 32, M, K, k0n + acf);
            rb = *(const uint4*)&BF[(size_t)(col0 + br) * K + k0n + bc];
        }

        #pragma unroll
        for (int ks = 0; ks < 32; ks += 16) {
            uint32_t ah[2][4], al[2][4], bf[4][2];
            int cc = ks + tig * 2;
            #pragma unroll
            for (int mt = 0; mt < 2; ++mt) {
                int r = wm * 32 + mt * 16 + gID;
                ah[mt][0] = *(const uint32_t*)&AsH[r][cc];
                ah[mt][1] = *(const uint32_t*)&AsH[r + 8][cc];
                ah[mt][2] = *(const uint32_t*)&AsH[r][cc + 8];
                ah[mt][3] = *(const uint32_t*)&AsH[r + 8][cc + 8];
                al[mt][0] = *(const uint32_t*)&AsL[r][cc];
                al[mt][1] = *(const uint32_t*)&AsL[r + 8][cc];
                al[mt][2] = *(const uint32_t*)&AsL[r][cc + 8];
                al[mt][3] = *(const uint32_t*)&AsL[r + 8][cc + 8];
            }
            #pragma unroll
            for (int nt = 0; nt < 4; ++nt) {
                int cr = wn * 32 + nt * 8 + gID;
                bf[nt][0] = *(const uint32_t*)&Bs[cr][cc];
                bf[nt][1] = *(const uint32_t*)&Bs[cr][cc + 8];
            }
            #pragma unroll
            for (int mt = 0; mt < 2; ++mt)
                #pragma unroll
                for (int nt = 0; nt < 4; ++nt) {
                    MMA16816F(acc[mt][nt], ah[mt], bf[nt]);
                    MMA16816F(acc[mt][nt], al[mt], bf[nt]);
                }
        }
        __syncthreads();
    }

    #pragma unroll
    for (int mt = 0; mt < 2; ++mt) {
        int r = row0 + wm * 32 + mt * 16 + gID;
        #pragma unroll
        for (int nt = 0; nt < 4; ++nt) {
            int c = col0 + wn * 32 + nt * 8 + tig * 2;
            float b0 = bias ? bias[c] : 0.f;
            float b1 = bias ? bias[c + 1] : 0.f;
            float v00 = acc[mt][nt][0] + b0, v01 = acc[mt][nt][1] + b1;
            float v10 = acc[mt][nt][2] + b0, v11 = acc[mt][nt][3] + b1;
            if (act) {
                v00 = v00 / (1.0f + expf(-v00));
                v01 = v01 / (1.0f + expf(-v01));
                v10 = v10 / (1.0f + expf(-v10));
                v11 = v11 / (1.0f + expf(-v11));
            }
            if (r < M)     { C[(size_t)r * N + c] = v00;       C[(size_t)r * N + c + 1] = v01; }
            if (r + 8 < M) { C[(size_t)(r + 8) * N + c] = v10; C[(size_t)(r + 8) * N + c + 1] = v11; }
        }
    }
}

// ---------------- per-edge contribution (full; fp32 gathers) ----------------
__device__ __forceinline__ void edge_body(const int* __restrict__ idx_j, int e, int t,
                                          float& aq, float& a0, float& a1, float& a2) {
    float4 g = g_geo[e];
    float d = g.w;
    if (d >= CUTOFF) return;
    int j = idx_j[e];

    float u = d * INV_STEP;
    int k = (int)u; if (k > NTAB - 2) k = NTAB - 2;
    float f = u - (float)k;
    const __half2* tp = &g_tab2[(size_t)k * F3];
    float2 p0 = __half22float2(tp[t]);
    float2 p1 = __half22float2(tp[F_DIM + t]);
    float2 p2 = __half22float2(tp[2 * F_DIM + t]);
    float w0 = fmaf(f, p0.y - p0.x, p0.x);
    float w1 = fmaf(f, p1.y - p1.x, p1.x);
    float w2 = fmaf(f, p2.y - p2.x, p2.x);

    const float* xr = &g_x[(size_t)j * F3];
    float xj0 = xr[t], xj1 = xr[F_DIM + t], xj2 = xr[2 * F_DIM + t];
    const float* mr = &g_mu[(size_t)j * 3 * F_DIM];
    float m0 = mr[t], m1 = mr[F_DIM + t], m2 = mr[2 * F_DIM + t];

    aq += w0 * xj0;
    float dmuR  = w1 * xj1;
    float dmumu = w2 * xj2;
    a0 += dmuR * g.x + dmumu * m0;
    a1 += dmuR * g.y + dmumu * m1;
    a2 += dmuR * g.z + dmumu * m2;
}

// ---------------- per-edge contribution, iteration 0 (mu == 0: no mu term) ----------------
__device__ __forceinline__ void edge_body0(const int* __restrict__ idx_j, int e, int t,
                                           float& aq, float& a0, float& a1, float& a2) {
    float4 g = g_geo[e];
    float d = g.w;
    if (d >= CUTOFF) return;
    int j = idx_j[e];

    float u = d * INV_STEP;
    int k = (int)u; if (k > NTAB - 2) k = NTAB - 2;
    float f = u - (float)k;
    const __half2* tp = &g_tab2[(size_t)k * F3];
    float2 p0 = __half22float2(tp[t]);
    float2 p1 = __half22float2(tp[F_DIM + t]);
    float w0 = fmaf(f, p0.y - p0.x, p0.x);
    float w1 = fmaf(f, p1.y - p1.x, p1.x);

    const float* xr = &g_x[(size_t)j * F3];
    float xj0 = xr[t], xj1 = xr[F_DIM + t];

    aq += w0 * xj0;
    float dmuR = w1 * xj1;
    a0 += dmuR * g.x;
    a1 += dmuR * g.y;
    a2 += dmuR * g.z;
}

// ---------------- CSR edge message pass: one block per atom, unroll-4 ----------------
__global__ void edge_message_csr(const int* __restrict__ idx_j) {
    int n = blockIdx.x, t = threadIdx.x;
    int e0 = g_row[n], e1 = g_row[n + 1];
    float aq0 = 0.f, x0 = 0.f, y0 = 0.f, z0 = 0.f;
    float aq1 = 0.f, x1 = 0.f, y1 = 0.f, z1 = 0.f;

    int e = e0;
    for (; e + 4 <= e1; e += 4) {
        edge_body(idx_j, e,     t, aq0, x0, y0, z0);
        edge_body(idx_j, e + 1, t, aq1, x1, y1, z1);
        edge_body(idx_j, e + 2, t, aq0, x0, y0, z0);
        edge_body(idx_j, e + 3, t, aq1, x1, y1, z1);
    }
    for (; e < e1; ++e) edge_body(idx_j, e, t, aq0, x0, y0, z0);

    g_q[n * F_DIM + t] += aq0 + aq1;
    g_dmu[(n * 3 + 0) * F_DIM + t] = x0 + x1;
    g_dmu[(n * 3 + 1) * F_DIM + t] = y0 + y1;
    g_dmu[(n * 3 + 2) * F_DIM + t] = z0 + z1;
}

__global__ void edge_message_csr0(const int* __restrict__ idx_j) {
    int n = blockIdx.x, t = threadIdx.x;
    int e0 = g_row[n], e1 = g_row[n + 1];
    float aq0 = 0.f, x0 = 0.f, y0 = 0.f, z0 = 0.f;
    float aq1 = 0.f, x1 = 0.f, y1 = 0.f, z1 = 0.f;

    int e = e0;
    for (; e + 4 <= e1; e += 4) {
        edge_body0(idx_j, e,     t, aq0, x0, y0, z0);
        edge_body0(idx_j, e + 1, t, aq1, x1, y1, z1);
        edge_body0(idx_j, e + 2, t, aq0, x0, y0, z0);
        edge_body0(idx_j, e + 3, t, aq1, x1, y1, z1);
    }
    for (; e < e1; ++e) edge_body0(idx_j, e, t, aq0, x0, y0, z0);

    g_q[n * F_DIM + t] += aq0 + aq1;
    g_dmu[(n * 3 + 0) * F_DIM + t] = x0 + x1;
    g_dmu[(n * 3 + 1) * F_DIM + t] = y0 + y1;
    g_dmu[(n * 3 + 2) * F_DIM + t] = z0 + z1;
}

// ---------------- mixing update: mu = (mu + dmu) + dmu_intra*muW; q += dq + dqmu*s ----------------
__global__ void mix_update() {
    int n = blockIdx.x, t = threadIdx.x;
    float dq   = g_xm[n * F3 + t];
    float dmu  = g_xm[n * F3 + F_DIM + t];
    float dqmu = g_xm[n * F3 + 2 * F_DIM + t];
    float s = 0.f;
    #pragma unroll
    for (int a = 0; a < 3; ++a) {
        float v = g_mumix[(n * 3 + a) * (2 * F_DIM) + t];
        float w = g_mumix[(n * 3 + a) * (2 * F_DIM) + F_DIM + t];
        s += v * w;
        g_mu[(n * 3 + a) * F_DIM + t] += g_dmu[(n * 3 + a) * F_DIM + t] + dmu * w;
    }
    g_q[n * F_DIM + t] += dq + dqmu * s;
}

// ================= host launch =================
extern "C" void kernel_launch(void* const* d_in, const int* in_sizes, int n_in,
                              void* d_out, int out_size) {
    (void)in_sizes; (void)n_in; (void)out_size;
    const int*   Z       = (const int*)  d_in[0];
    const float* R       = (const float*)d_in[1];
    const int*   idx_i   = (const int*)  d_in[2];
    const int*   idx_j   = (const int*)  d_in[3];
    const float* offs    = (const float*)d_in[4];
    const float* emb     = (const float*)d_in[5];
    const float* filt_W  = (const float*)d_in[6];
    const float* filt_b  = (const float*)d_in[7];
    const float* int_W1  = (const float*)d_in[8];
    const float* int_b1  = (const float*)d_in[9];
    const float* int_W2  = (const float*)d_in[10];
    const float* int_b2  = (const float*)d_in[11];
    const float* mix_Wmu = (const float*)d_in[12];
    const float* mix_W1  = (const float*)d_in[13];
    const float* mix_b1  = (const float*)d_in[14];
    const float* mix_W2  = (const float*)d_in[15];
    const float* mix_b2  = (const float*)d_in[16];
    float* out = (float*)d_out;

    void *p_q, *p_mu, *p_h, *p_x, *p_dmu, *p_mumix, *p_hm, *p_xm, *p_wF;
    cudaGetSymbolAddress(&p_q, g_q);
    cudaGetSymbolAddress(&p_mu, g_mu);
    cudaGetSymbolAddress(&p_h, g_h);
    cudaGetSymbolAddress(&p_x, g_x);
    cudaGetSymbolAddress(&p_dmu, g_dmu);
    cudaGetSymbolAddress(&p_mumix, g_mumix);
    cudaGetSymbolAddress(&p_hm, g_hm);
    cudaGetSymbolAddress(&p_xm, g_xm);
    cudaGetSymbolAddress(&p_wF, g_wF);

    fused_pre<<<NB_PRE, 384>>>(R, idx_i, idx_j, offs, filt_W, filt_b, Z, emb,
                               int_W1, int_W2, mix_Wmu, mix_W1, mix_W2);

    const __half* wF = (const __half*)p_wF;

    for (int it = 0; it < 3; ++it) {
        size_t wb = (size_t)it * WT_PER_ITER;

        // interaction MLP: q -> h (silu) -> x
        mma_gemm<0><<<dim3(2, 79), 256>>>(
            (const float*)p_q, nullptr, wF + wb + 0,
            int_b1 + (long)it * F_DIM, (float*)p_h, N_ATOMS, F_DIM, F_DIM, 1);
        mma_gemm<0><<<dim3(6, 79), 256>>>(
            (const float*)p_h, nullptr, wF + wb + 16384,
            int_b2 + (long)it * F3, (float*)p_x, N_ATOMS, F3, F_DIM, 0);

        // message pass (iter 0: mu == 0 -> reduced kernel)
        if (it == 0) edge_message_csr0<<<N_ATOMS, 128>>>(idx_j);
        else         edge_message_csr <<<N_ATOMS, 128>>>(idx_j);

        // mixing: mumix = (mu + dmu) @ Wmu   (iter 0: mu == 0 -> A = dmu directly)
        if (it == 0)
            mma_gemm<0><<<dim3(4, 235), 256>>>(
                (const float*)p_dmu, nullptr, wF + wb + 65536,
                nullptr, (float*)p_mumix, 3 * N_ATOMS, 2 * F_DIM, F_DIM, 0);
        else
            mma_gemm<1><<<dim3(4, 235), 256>>>(
                (const float*)p_mu, (const float*)p_dmu, wF + wb + 65536,
                nullptr, (float*)p_mumix, 3 * N_ATOMS, 2 * F_DIM, F_DIM, 0);

        // hm = silu([q, ||mu_V||] @ W1 + b1)  -- ctx synthesized in the A-loader
        mma_gemm<2><<<dim3(2, 79), 256>>>(
            (const float*)p_q, (const float*)p_mumix, wF + wb + 98304,
            mix_b1 + (long)it * F_DIM, (float*)p_hm, N_ATOMS, F_DIM, 2 * F_DIM, 1);
        mma_gemm<0><<<dim3(6, 79), 256>>>(
            (const float*)p_hm, nullptr, wF + wb + 131072,
            mix_b2 + (long)it * F3, (float*)p_xm, N_ATOMS, F3, F_DIM, 0);
        mix_update<<<N_ATOMS, 128>>>();
    }

    cudaMemcpyAsync(out, p_q, (size_t)N_ATOMS * F_DIM * sizeof(float),
                    cudaMemcpyDeviceToDevice);
    cudaMemcpyAsync(out + (size_t)N_ATOMS * F_DIM, p_mu,
                    (size_t)N_ATOMS * 3 * F_DIM * sizeof(float),
                    cudaMemcpyDeviceToDevice);
}

// round 14
// speedup vs baseline: 1.3058x; 1.1200x over previous
#include <cuda_runtime.h>
#include <cuda_bf16.h>
#include <cuda_fp16.h>
#include <math.h>
#include <stdint.h>

#define N_ATOMS 10000
#define N_EDGES 250000
#define F_DIM   128
#define F3      384
#define N_RBF   20
#define CUTOFF  5.0f
#define EPSV    1e-8f
#define NTAB    8192
#define INV_STEP ((float)(NTAB - 1) / CUTOFF)
#define WT_PER_ITER 180224   // 16384+49152+32768+32768+49152

// ---------------- scratch (device globals; no allocation allowed) ----------------
__device__ __half2 g_tab2[(size_t)NTAB * F3];
__device__ float4 g_geo [N_EDGES];
__device__ int    g_row [N_ATOMS + 1];
__device__ float g_q   [N_ATOMS * F_DIM];
__device__ float g_mu  [N_ATOMS * 3 * F_DIM];
__device__ float g_x   [N_ATOMS * F3];
__device__ float g_dmu [N_ATOMS * 3 * F_DIM];
__device__ float g_mumix[N_ATOMS * 3 * 2 * F_DIM];
__device__ float g_xm  [N_ATOMS * F3];
__device__ __half g_wF[3 * WT_PER_ITER];

__device__ __forceinline__ void split_f16(float v, __half& h, __half& l) {
    h = __float2half(v);
    l = __float2half(v - __half2float(h));
}
__device__ __forceinline__ float silu(float v) { return v / (1.0f + expf(-v)); }

#define MMA16816F(d, a, b) \
    asm volatile("mma.sync.aligned.m16n8k16.row.col.f32.f16.f16.f32 " \
        "{%0,%1,%2,%3}, {%4,%5,%6,%7}, {%8,%9}, {%0,%1,%2,%3};" \
        : "+f"((d)[0]), "+f"((d)[1]), "+f"((d)[2]), "+f"((d)[3]) \
        : "r"((a)[0]), "r"((a)[1]), "r"((a)[2]), "r"((a)[3]), \
          "r"((b)[0]), "r"((b)[1]))

// ================= fused precompute mega-kernel =================
#define NB_GEO ((N_EDGES + 383) / 384)
#define NB_ROW ((N_ATOMS + 384) / 384)
#define NB_PRE (NTAB + N_ATOMS + 2880 + NB_GEO + NB_ROW)

__global__ __launch_bounds__(384)
void fused_pre(const float* __restrict__ R,
               const int* __restrict__ idx_i, const int* __restrict__ idx_j,
               const float* __restrict__ offs,
               const float* __restrict__ filt_W, const float* __restrict__ filt_b,
               const int* __restrict__ Z, const float* __restrict__ emb,
               const float* __restrict__ W1, const float* __restrict__ W2,
               const float* __restrict__ Wmu, const float* __restrict__ M1,
               const float* __restrict__ M2) {
    int b = blockIdx.x, t = threadIdx.x;

    if (b < NTAB) {
        int k = b, c = t;
        __shared__ float s_phi[2][N_RBF];
        const float step = CUTOFF / (float)(NTAB - 1);
        float d0 = (float)k * step;
        int k1 = (k + 1 < NTAB) ? k + 1 : k;
        float d1 = (float)k1 * step;
        if (c < N_RBF) {
            const float spacing = CUTOFF / (float)(N_RBF - 1);
            const float coeff = -0.5f / (spacing * spacing);
            float dd0 = d0 - (float)c * spacing;
            float dd1 = d1 - (float)c * spacing;
            s_phi[0][c] = expf(coeff * dd0 * dd0);
            s_phi[1][c] = expf(coeff * dd1 * dd1);
        }
        __syncthreads();
        float fc0 = (d0 < CUTOFF) ? 0.5f * (cosf(d0 * (float)(M_PI / 5.0)) + 1.0f) : 0.0f;
        float fc1 = (d1 < CUTOFF) ? 0.5f * (cosf(d1 * (float)(M_PI / 5.0)) + 1.0f) : 0.0f;
        float a0 = filt_b[c], a1 = filt_b[c];
        #pragma unroll
        for (int r = 0; r < N_RBF; ++r) {
            float w = filt_W[r * F3 + c];
            a0 += s_phi[0][r] * w;
            a1 += s_phi[1][r] * w;
        }
        g_tab2[(size_t)k * F3 + c] = __floats2half2_rn(a0 * fc0, a1 * fc1);
        return;
    }
    b -= NTAB;

    if (b < N_ATOMS) {
        if (t < F_DIM) {
            int z = Z[b];
            g_q[b * F_DIM + t] = emb[z * F_DIM + t];
            #pragma unroll
            for (int a = 0; a < 3; ++a)
                g_mu[(b * 3 + a) * F_DIM + t] = 0.0f;
        }
        return;
    }
    b -= N_ATOMS;

    if (b < 2880) {
        if (t >= 256) return;
        const int Ks[5]  = {128, 128, 128, 256, 128};
        const int Ns[5]  = {128, 384, 256, 128, 384};
        const int off[5] = {0, 16384, 65536, 98304, 131072};
        int m = b / 192;
        int local = b % 192;
        int it = m / 5, s = m % 5;
        int K = Ks[s], N = Ns[s];
        int idx = local * 256 + t;
        if (idx >= K * N) return;
        const float* src;
        switch (s) {
            case 0: src = W1  + (size_t)it * 16384; break;
            case 1: src = W2  + (size_t)it * 49152; break;
            case 2: src = Wmu + (size_t)it * 32768; break;
            case 3: src = M1  + (size_t)it * 32768; break;
            default: src = M2 + (size_t)it * 49152; break;
        }
        int k = idx / N, n = idx % N;
        g_wF[(size_t)it * WT_PER_ITER + off[s] + (size_t)n * K + k] = __float2half(src[idx]);
        return;
    }
    b -= 2880;

    if (b < NB_GEO) {
        int e = b * 384 + t;
        if (e >= N_EDGES) return;
        int i = idx_i[e], j = idx_j[e];
        float rx = R[j*3+0] - R[i*3+0] + offs[e*3+0];
        float ry = R[j*3+1] - R[i*3+1] + offs[e*3+1];
        float rz = R[j*3+2] - R[i*3+2] + offs[e*3+2];
        float d = sqrtf(rx*rx + ry*ry + rz*rz);
        float inv = 1.0f / d;
        g_geo[e] = make_float4(rx*inv, ry*inv, rz*inv, d);
        return;
    }
    b -= NB_GEO;

    {
        int n = b * 384 + t;
        if (n > N_ATOMS) return;
        int lo = 0, hi = N_EDGES;
        while (lo < hi) {
            int mid = (lo + hi) >> 1;
            if (idx_i[mid] < n) lo = mid + 1; else hi = mid;
        }
        g_row[n] = lo;
    }
}

// ================= A-tile loader (compile-time MODE) =================
// MODE 0: A[gr*K + k]
// MODE 1: A[gr*K + k] + A2[gr*K + k]
// MODE 2: k<128 -> A(q); else ||mu_V|| from A2(mumix)
template<int MODE>
__device__ __forceinline__ float4 load_a(const float* __restrict__ A,
                                         const float* __restrict__ A2,
                                         int gr, int M, int K, int kcol) {
    if (gr >= M) return make_float4(0.f, 0.f, 0.f, 0.f);
    if (MODE == 0) {
        return *(const float4*)&A[(size_t)gr * K + kcol];
    } else if (MODE == 1) {
        float4 a = *(const float4*)&A[(size_t)gr * K + kcol];
        float4 b = *(const float4*)&A2[(size_t)gr * K + kcol];
        return make_float4(a.x + b.x, a.y + b.y, a.z + b.z, a.w + b.w);
    } else {
        if (kcol < 128) return *(const float4*)&A[(size_t)gr * 128 + kcol];
        int c = kcol - 128;
        float4 v0 = *(const float4*)&A2[((size_t)gr * 3 + 0) * 256 + c];
        float4 v1 = *(const float4*)&A2[((size_t)gr * 3 + 1) * 256 + c];
        float4 v2 = *(const float4*)&A2[((size_t)gr * 3 + 2) * 256 + c];
        return make_float4(
            sqrtf(EPSV + v0.x*v0.x + v1.x*v1.x + v2.x*v2.x),
            sqrtf(EPSV + v0.y*v0.y + v1.y*v1.y + v2.y*v2.y),
            sqrtf(EPSV + v0.z*v0.z + v1.z*v1.z + v2.z*v2.z),
            sqrtf(EPSV + v0.w*v0.w + v1.w*v1.w + v2.w*v2.w));
    }
}

// ================= fused 2-layer MLP: C[M,384] = silu(A@W1 + b1) @ W2 + b2 =================
// 64-row blocks, 256 threads (8 warps: 2m x 4n, warp tile 32x32). h held in smem fp16 hi/lo.
// dynamic smem layout (bytes):
#define FS_ASH1 0
#define FS_ASL1 5120
#define FS_BS1  10240         // [128][40] half
#define FS_HH   20480         // [64][136] half
#define FS_HL   37888
#define FS_BS2  55296         // [128][136] half
#define FS_TOTAL 90112

template<int MODE>
__global__ __launch_bounds__(256)
void fused_mlp(const float* __restrict__ A, const float* __restrict__ A2,
               const __half* __restrict__ W1f, const float* __restrict__ b1,
               const __half* __restrict__ W2f, const float* __restrict__ b2,
               float* __restrict__ C, int M, int K1) {
    extern __shared__ char smem[];
    __half (*AsH1)[40]  = (__half(*)[40])(smem + FS_ASH1);
    __half (*AsL1)[40]  = (__half(*)[40])(smem + FS_ASL1);
    __half (*Bs1)[40]   = (__half(*)[40])(smem + FS_BS1);
    __half (*hH)[136]   = (__half(*)[136])(smem + FS_HH);
    __half (*hL)[136]   = (__half(*)[136])(smem + FS_HL);
    __half (*Bs2)[136]  = (__half(*)[136])(smem + FS_BS2);

    int tid = threadIdx.x, wid = tid >> 5, lane = tid & 31;
    int row0 = blockIdx.x * 64;
    int wm = wid >> 2, wn = wid & 3;        // 2m x 4n
    int gID = lane >> 2, tig = lane & 3;

    // ---------- stage 1: h = silu(A @ W1 + b1), N=128 ----------
    float acc[2][4][4];
    #pragma unroll
    for (int mt = 0; mt < 2; ++mt)
        #pragma unroll
        for (int nt = 0; nt < 4; ++nt)
            #pragma unroll
            for (int i = 0; i < 4; ++i) acc[mt][nt][i] = 0.f;

    int nc = K1 >> 5;
    float4 ra[2];
    uint4 rb1[2];
    // A stage map: 512 float4 (64 rows x 8 f4) -> 2/thread
    int ar[2], ac[2];
    #pragma unroll
    for (int p = 0; p < 2; ++p) {
        int idx = tid + p * 256;
        ar[p] = idx >> 3; ac[p] = (idx & 7) * 4;
    }
    // B1 stage map: 512 uint4 (128 rows x 4 u4) -> 2/thread
    int bn[2], bk[2];
    #pragma unroll
    for (int p = 0; p < 2; ++p) {
        int idx = tid + p * 256;
        bn[p] = idx >> 2; bk[p] = (idx & 3) * 8;
    }

    #pragma unroll
    for (int p = 0; p < 2; ++p) {
        ra[p] = load_a<MODE>(A, A2, row0 + ar[p], M, K1, ac[p]);
        rb1[p] = *(const uint4*)&W1f[(size_t)bn[p] * K1 + bk[p]];
    }

    for (int c = 0; c < nc; ++c) {
        #pragma unroll
        for (int p = 0; p < 2; ++p) {
            __half h, l;
            split_f16(ra[p].x, h, l); AsH1[ar[p]][ac[p]+0] = h; AsL1[ar[p]][ac[p]+0] = l;
            split_f16(ra[p].y, h, l); AsH1[ar[p]][ac[p]+1] = h; AsL1[ar[p]][ac[p]+1] = l;
            split_f16(ra[p].z, h, l); AsH1[ar[p]][ac[p]+2] = h; AsL1[ar[p]][ac[p]+2] = l;
            split_f16(ra[p].w, h, l); AsH1[ar[p]][ac[p]+3] = h; AsL1[ar[p]][ac[p]+3] = l;
            *(uint4*)&Bs1[bn[p]][bk[p]] = rb1[p];
        }
        __syncthreads();

        if (c + 1 < nc) {
            int k0n = (c + 1) << 5;
            #pragma unroll
            for (int p = 0; p < 2; ++p) {
                ra[p] = load_a<MODE>(A, A2, row0 + ar[p], M, K1, k0n + ac[p]);
                rb1[p] = *(const uint4*)&W1f[(size_t)bn[p] * K1 + k0n + bk[p]];
            }
        }

        #pragma unroll
        for (int ks = 0; ks < 32; ks += 16) {
            uint32_t ah[2][4], al[2][4], bf[4][2];
            int cc = ks + tig * 2;
            #pragma unroll
            for (int mt = 0; mt < 2; ++mt) {
                int r = wm * 32 + mt * 16 + gID;
                ah[mt][0] = *(const uint32_t*)&AsH1[r][cc];
                ah[mt][1] = *(const uint32_t*)&AsH1[r + 8][cc];
                ah[mt][2] = *(const uint32_t*)&AsH1[r][cc + 8];
                ah[mt][3] = *(const uint32_t*)&AsH1[r + 8][cc + 8];
                al[mt][0] = *(const uint32_t*)&AsL1[r][cc];
                al[mt][1] = *(const uint32_t*)&AsL1[r + 8][cc];
                al[mt][2] = *(const uint32_t*)&AsL1[r][cc + 8];
                al[mt][3] = *(const uint32_t*)&AsL1[r + 8][cc + 8];
            }
            #pragma unroll
            for (int nt = 0; nt < 4; ++nt) {
                int cr = wn * 32 + nt * 8 + gID;
                bf[nt][0] = *(const uint32_t*)&Bs1[cr][cc];
                bf[nt][1] = *(const uint32_t*)&Bs1[cr][cc + 8];
            }
            #pragma unroll
            for (int mt = 0; mt < 2; ++mt)
                #pragma unroll
                for (int nt = 0; nt < 4; ++nt) {
                    MMA16816F(acc[mt][nt], ah[mt], bf[nt]);
                    MMA16816F(acc[mt][nt], al[mt], bf[nt]);
                }
        }
        __syncthreads();
    }

    // stage-1 epilogue: silu(acc + b1) -> hH/hL smem (fp16 split)
    #pragma unroll
    for (int mt = 0; mt < 2; ++mt) {
        int r = wm * 32 + mt * 16 + gID;
        #pragma unroll
        for (int nt = 0; nt < 4; ++nt) {
            int c = wn * 32 + nt * 8 + tig * 2;
            float b0 = b1[c], bb1 = b1[c + 1];
            float v00 = silu(acc[mt][nt][0] + b0), v01 = silu(acc[mt][nt][1] + bb1);
            float v10 = silu(acc[mt][nt][2] + b0), v11 = silu(acc[mt][nt][3] + bb1);
            __half h, l;
            split_f16(v00, h, l); hH[r][c]       = h; hL[r][c]       = l;
            split_f16(v01, h, l); hH[r][c + 1]   = h; hL[r][c + 1]   = l;
            split_f16(v10, h, l); hH[r + 8][c]   = h; hL[r + 8][c]   = l;
            split_f16(v11, h, l); hH[r + 8][c+1] = h; hL[r + 8][c+1] = l;
        }
    }
    __syncthreads();

    // ---------- stage 2: C = h @ W2 + b2, N=384 in 3 chunks of 128 ----------
    for (int ch = 0; ch < 3; ++ch) {
        // load W2 chunk [128 n][128 k]: 2048 uint4 -> 8/thread
        #pragma unroll
        for (int p = 0; p < 8; ++p) {
            int idx = tid + p * 256;
            int n = idx >> 4, kc = (idx & 15) * 8;
            *(uint4*)&Bs2[n][kc] = *(const uint4*)&W2f[(size_t)(ch * 128 + n) * 128 + kc];
        }
        __syncthreads();

        float acc2[2][4][4];
        #pragma unroll
        for (int mt = 0; mt < 2; ++mt)
            #pragma unroll
            for (int nt = 0; nt < 4; ++nt)
                #pragma unroll
                for (int i = 0; i < 4; ++i) acc2[mt][nt][i] = 0.f;

        #pragma unroll
        for (int ks = 0; ks < 128; ks += 16) {
            uint32_t ah[2][4], al[2][4], bf[4][2];
            int cc = ks + tig * 2;
            #pragma unroll
            for (int mt = 0; mt < 2; ++mt) {
                int r = wm * 32 + mt * 16 + gID;
                ah[mt][0] = *(const uint32_t*)&hH[r][cc];
                ah[mt][1] = *(const uint32_t*)&hH[r + 8][cc];
                ah[mt][2] = *(const uint32_t*)&hH[r][cc + 8];
                ah[mt][3] = *(const uint32_t*)&hH[r + 8][cc + 8];
                al[mt][0] = *(const uint32_t*)&hL[r][cc];
                al[mt][1] = *(const uint32_t*)&hL[r + 8][cc];
                al[mt][2] = *(const uint32_t*)&hL[r][cc + 8];
                al[mt][3] = *(const uint32_t*)&hL[r + 8][cc + 8];
            }
            #pragma unroll
            for (int nt = 0; nt < 4; ++nt) {
                int cr = wn * 32 + nt * 8 + gID;
                bf[nt][0] = *(const uint32_t*)&Bs2[cr][cc];
                bf[nt][1] = *(const uint32_t*)&Bs2[cr][cc + 8];
            }
            #pragma unroll
            for (int mt = 0; mt < 2; ++mt)
                #pragma unroll
                for (int nt = 0; nt < 4; ++nt) {
                    MMA16816F(acc2[mt][nt], ah[mt], bf[nt]);
                    MMA16816F(acc2[mt][nt], al[mt], bf[nt]);
                }
        }

        #pragma unroll
        for (int mt = 0; mt < 2; ++mt) {
            int r = row0 + wm * 32 + mt * 16 + gID;
            #pragma unroll
            for (int nt = 0; nt < 4; ++nt) {
                int c = ch * 128 + wn * 32 + nt * 8 + tig * 2;
                float b0 = b2[c], bb = b2[c + 1];
                if (r < M) {
                    C[(size_t)r * F3 + c]     = acc2[mt][nt][0] + b0;
                    C[(size_t)r * F3 + c + 1] = acc2[mt][nt][1] + bb;
                }
                if (r + 8 < M) {
                    C[(size_t)(r + 8) * F3 + c]     = acc2[mt][nt][2] + b0;
                    C[(size_t)(r + 8) * F3 + c + 1] = acc2[mt][nt][3] + bb;
                }
            }
        }
        if (ch < 2) __syncthreads();
    }
}

// ================= plain GEMM (for mumix): C = A @ W, N=256 =================
template<int MODE>
__global__ __launch_bounds__(256)
void mma_gemm(const float* __restrict__ A, const float* __restrict__ A2,
              const __half* __restrict__ BF, float* __restrict__ C,
              int M, int N, int K) {
    __shared__ __half AsH[128][40], AsL[128][40];
    __shared__ __half Bs[64][40];

    int tid = threadIdx.x, wid = tid >> 5, lane = tid & 31;
    int row0 = blockIdx.y * 128, col0 = blockIdx.x * 64;
    int wm = wid >> 1, wn = wid & 1;
    int gID = lane >> 2, tig = lane & 3;

    float acc[2][4][4];
    #pragma unroll
    for (int mt = 0; mt < 2; ++mt)
        #pragma unroll
        for (int nt = 0; nt < 4; ++nt)
            #pragma unroll
            for (int i = 0; i < 4; ++i) acc[mt][nt][i] = 0.f;

    int nc = K >> 5;
    float4 ra[4];
    uint4 rb;
    int br = tid >> 2, bc = (tid & 3) * 8;
    int arf = tid >> 3, acf = (tid & 7) * 4;

    #pragma unroll
    for (int p = 0; p < 4; ++p)
        ra[p] = load_a<MODE>(A, A2, row0 + arf + p * 32, M, K, acf);
    rb = *(const uint4*)&BF[(size_t)(col0 + br) * K + bc];

    for (int c = 0; c < nc; ++c) {
        #pragma unroll
        for (int p = 0; p < 4; ++p) {
            int r = arf + p * 32;
            __half h, l;
            split_f16(ra[p].x, h, l); AsH[r][acf+0] = h; AsL[r][acf+0] = l;
            split_f16(ra[p].y, h, l); AsH[r][acf+1] = h; AsL[r][acf+1] = l;
            split_f16(ra[p].z, h, l); AsH[r][acf+2] = h; AsL[r][acf+2] = l;
            split_f16(ra[p].w, h, l); AsH[r][acf+3] = h; AsL[r][acf+3] = l;
        }
        *(uint4*)&Bs[br][bc] = rb;
        __syncthreads();

        if (c + 1 < nc) {
            int k0n = (c + 1) << 5;
            #pragma unroll
            for (int p = 0; p < 4; ++p)
                ra[p] = load_a<MODE>(A, A2, row0 + arf + p * 32, M, K, k0n + acf);
            rb = *(const uint4*)&BF[(size_t)(col0 + br) * K + k0n + bc];
        }

        #pragma unroll
        for (int ks = 0; ks < 32; ks += 16) {
            uint32_t ah[2][4], al[2][4], bf[4][2];
            int cc = ks + tig * 2;
            #pragma unroll
            for (int mt = 0; mt < 2; ++mt) {
                int r = wm * 32 + mt * 16 + gID;
                ah[mt][0] = *(const uint32_t*)&AsH[r][cc];
                ah[mt][1] = *(const uint32_t*)&AsH[r + 8][cc];
                ah[mt][2] = *(const uint32_t*)&AsH[r][cc + 8];
                ah[mt][3] = *(const uint32_t*)&AsH[r + 8][cc + 8];
                al[mt][0] = *(const uint32_t*)&AsL[r][cc];
                al[mt][1] = *(const uint32_t*)&AsL[r + 8][cc];
                al[mt][2] = *(const uint32_t*)&AsL[r][cc + 8];
                al[mt][3] = *(const uint32_t*)&AsL[r + 8][cc + 8];
            }
            #pragma unroll
            for (int nt = 0; nt < 4; ++nt) {
                int cr = wn * 32 + nt * 8 + gID;
                bf[nt][0] = *(const uint32_t*)&Bs[cr][cc];
                bf[nt][1] = *(const uint32_t*)&Bs[cr][cc + 8];
            }
            #pragma unroll
            for (int mt = 0; mt < 2; ++mt)
                #pragma unroll
                for (int nt = 0; nt < 4; ++nt) {
                    MMA16816F(acc[mt][nt], ah[mt], bf[nt]);
                    MMA16816F(acc[mt][nt], al[mt], bf[nt]);
                }
        }
        __syncthreads();
    }

    #pragma unroll
    for (int mt = 0; mt < 2; ++mt) {
        int r = row0 + wm * 32 + mt * 16 + gID;
        #pragma unroll
        for (int nt = 0; nt < 4; ++nt) {
            int c = col0 + wn * 32 + nt * 8 + tig * 2;
            if (r < M) {
                C[(size_t)r * N + c]     = acc[mt][nt][0];
                C[(size_t)r * N + c + 1] = acc[mt][nt][1];
            }
            if (r + 8 < M) {
                C[(size_t)(r + 8) * N + c]     = acc[mt][nt][2];
                C[(size_t)(r + 8) * N + c + 1] = acc[mt][nt][3];
            }
        }
    }
}

// ---------------- per-edge contribution (full) ----------------
__device__ __forceinline__ void edge_body(const int* __restrict__ idx_j, int e, int t,
                                          float& aq, float& a0, float& a1, float& a2) {
    float4 g = g_geo[e];
    float d = g.w;
    if (d >= CUTOFF) return;
    int j = idx_j[e];

    float u = d * INV_STEP;
    int k = (int)u; if (k > NTAB - 2) k = NTAB - 2;
    float f = u - (float)k;
    const __half2* tp = &g_tab2[(size_t)k * F3];
    float2 p0 = __half22float2(tp[t]);
    float2 p1 = __half22float2(tp[F_DIM + t]);
    float2 p2 = __half22float2(tp[2 * F_DIM + t]);
    float w0 = fmaf(f, p0.y - p0.x, p0.x);
    float w1 = fmaf(f, p1.y - p1.x, p1.x);
    float w2 = fmaf(f, p2.y - p2.x, p2.x);

    const float* xr = &g_x[(size_t)j * F3];
    float xj0 = xr[t], xj1 = xr[F_DIM + t], xj2 = xr[2 * F_DIM + t];
    const float* mr = &g_mu[(size_t)j * 3 * F_DIM];
    float m0 = mr[t], m1 = mr[F_DIM + t], m2 = mr[2 * F_DIM + t];

    aq += w0 * xj0;
    float dmuR  = w1 * xj1;
    float dmumu = w2 * xj2;
    a0 += dmuR * g.x + dmumu * m0;
    a1 += dmuR * g.y + dmumu * m1;
    a2 += dmuR * g.z + dmumu * m2;
}

// ---------------- per-edge contribution, iteration 0 (mu == 0) ----------------
__device__ __forceinline__ void edge_body0(const int* __restrict__ idx_j, int e, int t,
                                           float& aq, float& a0, float& a1, float& a2) {
    float4 g = g_geo[e];
    float d = g.w;
    if (d >= CUTOFF) return;
    int j = idx_j[e];

    float u = d * INV_STEP;
    int k = (int)u; if (k > NTAB - 2) k = NTAB - 2;
    float f = u - (float)k;
    const __half2* tp = &g_tab2[(size_t)k * F3];
    float2 p0 = __half22float2(tp[t]);
    float2 p1 = __half22float2(tp[F_DIM + t]);
    float w0 = fmaf(f, p0.y - p0.x, p0.x);
    float w1 = fmaf(f, p1.y - p1.x, p1.x);

    const float* xr = &g_x[(size_t)j * F3];
    float xj0 = xr[t], xj1 = xr[F_DIM + t];

    aq += w0 * xj0;
    float dmuR = w1 * xj1;
    a0 += dmuR * g.x;
    a1 += dmuR * g.y;
    a2 += dmuR * g.z;
}

__global__ void edge_message_csr(const int* __restrict__ idx_j) {
    int n = blockIdx.x, t = threadIdx.x;
    int e0 = g_row[n], e1 = g_row[n + 1];
    float aq0 = 0.f, x0 = 0.f, y0 = 0.f, z0 = 0.f;
    float aq1 = 0.f, x1 = 0.f, y1 = 0.f, z1 = 0.f;

    int e = e0;
    for (; e + 4 <= e1; e += 4) {
        edge_body(idx_j, e,     t, aq0, x0, y0, z0);
        edge_body(idx_j, e + 1, t, aq1, x1, y1, z1);
        edge_body(idx_j, e + 2, t, aq0, x0, y0, z0);
        edge_body(idx_j, e + 3, t, aq1, x1, y1, z1);
    }
    for (; e < e1; ++e) edge_body(idx_j, e, t, aq0, x0, y0, z0);

    g_q[n * F_DIM + t] += aq0 + aq1;
    g_dmu[(n * 3 + 0) * F_DIM + t] = x0 + x1;
    g_dmu[(n * 3 + 1) * F_DIM + t] = y0 + y1;
    g_dmu[(n * 3 + 2) * F_DIM + t] = z0 + z1;
}

__global__ void edge_message_csr0(const int* __restrict__ idx_j) {
    int n = blockIdx.x, t = threadIdx.x;
    int e0 = g_row[n], e1 = g_row[n + 1];
    float aq0 = 0.f, x0 = 0.f, y0 = 0.f, z0 = 0.f;
    float aq1 = 0.f, x1 = 0.f, y1 = 0.f, z1 = 0.f;

    int e = e0;
    for (; e + 4 <= e1; e += 4) {
        edge_body0(idx_j, e,     t, aq0, x0, y0, z0);
        edge_body0(idx_j, e + 1, t, aq1, x1, y1, z1);
        edge_body0(idx_j, e + 2, t, aq0, x0, y0, z0);
        edge_body0(idx_j, e + 3, t, aq1, x1, y1, z1);
    }
    for (; e < e1; ++e) edge_body0(idx_j, e, t, aq0, x0, y0, z0);

    g_q[n * F_DIM + t] += aq0 + aq1;
    g_dmu[(n * 3 + 0) * F_DIM + t] = x0 + x1;
    g_dmu[(n * 3 + 1) * F_DIM + t] = y0 + y1;
    g_dmu[(n * 3 + 2) * F_DIM + t] = z0 + z1;
}

// ---------------- mixing update ----------------
__global__ void mix_update() {
    int n = blockIdx.x, t = threadIdx.x;
    float dq   = g_xm[n * F3 + t];
    float dmu  = g_xm[n * F3 + F_DIM + t];
    float dqmu = g_xm[n * F3 + 2 * F_DIM + t];
    float s = 0.f;
    #pragma unroll
    for (int a = 0; a < 3; ++a) {
        float v = g_mumix[(n * 3 + a) * (2 * F_DIM) + t];
        float w = g_mumix[(n * 3 + a) * (2 * F_DIM) + F_DIM + t];
        s += v * w;
        g_mu[(n * 3 + a) * F_DIM + t] += g_dmu[(n * 3 + a) * F_DIM + t] + dmu * w;
    }
    g_q[n * F_DIM + t] += dq + dqmu * s;
}

// ================= host launch =================
extern "C" void kernel_launch(void* const* d_in, const int* in_sizes, int n_in,
                              void* d_out, int out_size) {
    (void)in_sizes; (void)n_in; (void)out_size;
    const int*   Z       = (const int*)  d_in[0];
    const float* R       = (const float*)d_in[1];
    const int*   idx_i   = (const int*)  d_in[2];
    const int*   idx_j   = (const int*)  d_in[3];
    const float* offs    = (const float*)d_in[4];
    const float* emb     = (const float*)d_in[5];
    const float* filt_W  = (const float*)d_in[6];
    const float* filt_b  = (const float*)d_in[7];
    const float* int_W1  = (const float*)d_in[8];
    const float* int_b1  = (const float*)d_in[9];
    const float* int_W2  = (const float*)d_in[10];
    const float* int_b2  = (const float*)d_in[11];
    const float* mix_Wmu = (const float*)d_in[12];
    const float* mix_W1  = (const float*)d_in[13];
    const float* mix_b1  = (const float*)d_in[14];
    const float* mix_W2  = (const float*)d_in[15];
    const float* mix_b2  = (const float*)d_in[16];
    float* out = (float*)d_out;

    void *p_q, *p_mu, *p_x, *p_dmu, *p_mumix, *p_xm, *p_wF;
    cudaGetSymbolAddress(&p_q, g_q);
    cudaGetSymbolAddress(&p_mu, g_mu);
    cudaGetSymbolAddress(&p_x, g_x);
    cudaGetSymbolAddress(&p_dmu, g_dmu);
    cudaGetSymbolAddress(&p_mumix, g_mumix);
    cudaGetSymbolAddress(&p_xm, g_xm);
    cudaGetSymbolAddress(&p_wF, g_wF);

    cudaFuncSetAttribute(fused_mlp<0>, cudaFuncAttributeMaxDynamicSharedMemorySize, FS_TOTAL);
    cudaFuncSetAttribute(fused_mlp<2>, cudaFuncAttributeMaxDynamicSharedMemorySize, FS_TOTAL);

    fused_pre<<<NB_PRE, 384>>>(R, idx_i, idx_j, offs, filt_W, filt_b, Z, emb,
                               int_W1, int_W2, mix_Wmu, mix_W1, mix_W2);

    const __half* wF = (const __half*)p_wF;
    const int NBLK = (N_ATOMS + 63) / 64;     // 157

    for (int it = 0; it < 3; ++it) {
        size_t wb = (size_t)it * WT_PER_ITER;

        // interaction MLP fused: x = silu(q@W1+b1)@W2+b2
        fused_mlp<0><<<NBLK, 256, FS_TOTAL>>>(
            (const float*)p_q, nullptr,
            wF + wb + 0, int_b1 + (long)it * F_DIM,
            wF + wb + 16384, int_b2 + (long)it * F3,
            (float*)p_x, N_ATOMS, F_DIM);

        // message pass
        if (it == 0) edge_message_csr0<<<N_ATOMS, 128>>>(idx_j);
        else         edge_message_csr <<<N_ATOMS, 128>>>(idx_j);

        // mumix = (mu + dmu) @ Wmu
        if (it == 0)
            mma_gemm<0><<<dim3(4, 235), 256>>>(
                (const float*)p_dmu, nullptr, wF + wb + 65536,
                (float*)p_mumix, 3 * N_ATOMS, 2 * F_DIM, F_DIM);
        else
            mma_gemm<1><<<dim3(4, 235), 256>>>(
                (const float*)p_mu, (const float*)p_dmu, wF + wb + 65536,
                (float*)p_mumix, 3 * N_ATOMS, 2 * F_DIM, F_DIM);

        // mixing MLP fused: xm = silu([q,||mu_V||]@W1+b1)@W2+b2 (ctx synthesized)
        fused_mlp<2><<<NBLK, 256, FS_TOTAL>>>(
            (const float*)p_q, (const float*)p_mumix,
            wF + wb + 98304, mix_b1 + (long)it * F_DIM,
            wF + wb + 131072, mix_b2 + (long)it * F3,
            (float*)p_xm, N_ATOMS, 2 * F_DIM);

        mix_update<<<N_ATOMS, 128>>>();
    }

    cudaMemcpyAsync(out, p_q, (size_t)N_ATOMS * F_DIM * sizeof(float),
                    cudaMemcpyDeviceToDevice);
    cudaMemcpyAsync(out + (size_t)N_ATOMS * F_DIM, p_mu,
                    (size_t)N_ATOMS * 3 * F_DIM * sizeof(float),
                    cudaMemcpyDeviceToDevice);
}

// round 15
// speedup vs baseline: 1.3492x; 1.0333x over previous
#include <cuda_runtime.h>
#include <cuda_bf16.h>
#include <cuda_fp16.h>
#include <math.h>
#include <stdint.h>

#define N_ATOMS 10000
#define N_EDGES 250000
#define F_DIM   128
#define F3      384
#define N_RBF   20
#define CUTOFF  5.0f
#define EPSV    1e-8f
#define NTAB    8192
#define INV_STEP ((float)(NTAB - 1) / CUTOFF)
#define WT_PER_ITER 180224   // 16384+49152+32768+32768+49152

// ---------------- scratch (device globals; no allocation allowed) ----------------
__device__ __half2 g_tab2[(size_t)NTAB * F3];
__device__ float4 g_geo [N_EDGES];
__device__ int    g_row [N_ATOMS + 1];
__device__ float g_q   [N_ATOMS * F_DIM];
__device__ float g_mu  [N_ATOMS * 3 * F_DIM];
__device__ float g_x   [N_ATOMS * F3];
__device__ float g_dmu [N_ATOMS * 3 * F_DIM];
__device__ float g_mumix[N_ATOMS * 3 * 2 * F_DIM];
__device__ float g_xm  [N_ATOMS * F3];
__device__ __half g_wF[3 * WT_PER_ITER];

__device__ __forceinline__ void split_f16(float v, __half& h, __half& l) {
    h = __float2half(v);
    l = __float2half(v - __half2float(h));
}
__device__ __forceinline__ float silu(float v) { return v / (1.0f + expf(-v)); }

// pack a float4's hi/lo fp16 splits into two uint2 (4 halves each)
__device__ __forceinline__ void split4_pack(float4 v, uint2& hh, uint2& ll) {
    __half hx, lx, hy, ly, hz, lz, hw, lw;
    split_f16(v.x, hx, lx); split_f16(v.y, hy, ly);
    split_f16(v.z, hz, lz); split_f16(v.w, hw, lw);
    __half2 h01 = __halves2half2(hx, hy), h23 = __halves2half2(hz, hw);
    __half2 l01 = __halves2half2(lx, ly), l23 = __halves2half2(lz, lw);
    hh.x = *(uint32_t*)&h01; hh.y = *(uint32_t*)&h23;
    ll.x = *(uint32_t*)&l01; ll.y = *(uint32_t*)&l23;
}

#define MMA16816F(d, a, b) \
    asm volatile("mma.sync.aligned.m16n8k16.row.col.f32.f16.f16.f32 " \
        "{%0,%1,%2,%3}, {%4,%5,%6,%7}, {%8,%9}, {%0,%1,%2,%3};" \
        : "+f"((d)[0]), "+f"((d)[1]), "+f"((d)[2]), "+f"((d)[3]) \
        : "r"((a)[0]), "r"((a)[1]), "r"((a)[2]), "r"((a)[3]), \
          "r"((b)[0]), "r"((b)[1]))

// ================= fused precompute mega-kernel =================
#define NB_GEO ((N_EDGES + 383) / 384)
#define NB_ROW ((N_ATOMS + 384) / 384)
#define NB_PRE (NTAB + N_ATOMS + 2880 + NB_GEO + NB_ROW)

__global__ __launch_bounds__(384)
void fused_pre(const float* __restrict__ R,
               const int* __restrict__ idx_i, const int* __restrict__ idx_j,
               const float* __restrict__ offs,
               const float* __restrict__ filt_W, const float* __restrict__ filt_b,
               const int* __restrict__ Z, const float* __restrict__ emb,
               const float* __restrict__ W1, const float* __restrict__ W2,
               const float* __restrict__ Wmu, const float* __restrict__ M1,
               const float* __restrict__ M2) {
    int b = blockIdx.x, t = threadIdx.x;

    if (b < NTAB) {
        int k = b, c = t;
        __shared__ float s_phi[2][N_RBF];
        const float step = CUTOFF / (float)(NTAB - 1);
        float d0 = (float)k * step;
        int k1 = (k + 1 < NTAB) ? k + 1 : k;
        float d1 = (float)k1 * step;
        if (c < N_RBF) {
            const float spacing = CUTOFF / (float)(N_RBF - 1);
            const float coeff = -0.5f / (spacing * spacing);
            float dd0 = d0 - (float)c * spacing;
            float dd1 = d1 - (float)c * spacing;
            s_phi[0][c] = expf(coeff * dd0 * dd0);
            s_phi[1][c] = expf(coeff * dd1 * dd1);
        }
        __syncthreads();
        float fc0 = (d0 < CUTOFF) ? 0.5f * (cosf(d0 * (float)(M_PI / 5.0)) + 1.0f) : 0.0f;
        float fc1 = (d1 < CUTOFF) ? 0.5f * (cosf(d1 * (float)(M_PI / 5.0)) + 1.0f) : 0.0f;
        float a0 = filt_b[c], a1 = filt_b[c];
        #pragma unroll
        for (int r = 0; r < N_RBF; ++r) {
            float w = filt_W[r * F3 + c];
            a0 += s_phi[0][r] * w;
            a1 += s_phi[1][r] * w;
        }
        g_tab2[(size_t)k * F3 + c] = __floats2half2_rn(a0 * fc0, a1 * fc1);
        return;
    }
    b -= NTAB;

    if (b < N_ATOMS) {
        if (t < F_DIM) {
            int z = Z[b];
            g_q[b * F_DIM + t] = emb[z * F_DIM + t];
            #pragma unroll
            for (int a = 0; a < 3; ++a)
                g_mu[(b * 3 + a) * F_DIM + t] = 0.0f;
        }
        return;
    }
    b -= N_ATOMS;

    if (b < 2880) {
        if (t >= 256) return;
        const int Ks[5]  = {128, 128, 128, 256, 128};
        const int Ns[5]  = {128, 384, 256, 128, 384};
        const int off[5] = {0, 16384, 65536, 98304, 131072};
        int m = b / 192;
        int local = b % 192;
        int it = m / 5, s = m % 5;
        int K = Ks[s], N = Ns[s];
        int idx = local * 256 + t;
        if (idx >= K * N) return;
        const float* src;
        switch (s) {
            case 0: src = W1  + (size_t)it * 16384; break;
            case 1: src = W2  + (size_t)it * 49152; break;
            case 2: src = Wmu + (size_t)it * 32768; break;
            case 3: src = M1  + (size_t)it * 32768; break;
            default: src = M2 + (size_t)it * 49152; break;
        }
        int k = idx / N, n = idx % N;
        g_wF[(size_t)it * WT_PER_ITER + off[s] + (size_t)n * K + k] = __float2half(src[idx]);
        return;
    }
    b -= 2880;

    if (b < NB_GEO) {
        int e = b * 384 + t;
        if (e >= N_EDGES) return;
        int i = idx_i[e], j = idx_j[e];
        float rx = R[j*3+0] - R[i*3+0] + offs[e*3+0];
        float ry = R[j*3+1] - R[i*3+1] + offs[e*3+1];
        float rz = R[j*3+2] - R[i*3+2] + offs[e*3+2];
        float d = sqrtf(rx*rx + ry*ry + rz*rz);
        float inv = 1.0f / d;
        g_geo[e] = make_float4(rx*inv, ry*inv, rz*inv, d);
        return;
    }
    b -= NB_GEO;

    {
        int n = b * 384 + t;
        if (n > N_ATOMS) return;
        int lo = 0, hi = N_EDGES;
        while (lo < hi) {
            int mid = (lo + hi) >> 1;
            if (idx_i[mid] < n) lo = mid + 1; else hi = mid;
        }
        g_row[n] = lo;
    }
}

// ================= A-tile loader (compile-time MODE) =================
template<int MODE>
__device__ __forceinline__ float4 load_a(const float* __restrict__ A,
                                         const float* __restrict__ A2,
                                         int gr, int M, int K, int kcol) {
    if (gr >= M) return make_float4(0.f, 0.f, 0.f, 0.f);
    if (MODE == 0) {
        return *(const float4*)&A[(size_t)gr * K + kcol];
    } else if (MODE == 1) {
        float4 a = *(const float4*)&A[(size_t)gr * K + kcol];
        float4 b = *(const float4*)&A2[(size_t)gr * K + kcol];
        return make_float4(a.x + b.x, a.y + b.y, a.z + b.z, a.w + b.w);
    } else {
        if (kcol < 128) return *(const float4*)&A[(size_t)gr * 128 + kcol];
        int c = kcol - 128;
        float4 v0 = *(const float4*)&A2[((size_t)gr * 3 + 0) * 256 + c];
        float4 v1 = *(const float4*)&A2[((size_t)gr * 3 + 1) * 256 + c];
        float4 v2 = *(const float4*)&A2[((size_t)gr * 3 + 2) * 256 + c];
        return make_float4(
            sqrtf(EPSV + v0.x*v0.x + v1.x*v1.x + v2.x*v2.x),
            sqrtf(EPSV + v0.y*v0.y + v1.y*v1.y + v2.y*v2.y),
            sqrtf(EPSV + v0.z*v0.z + v1.z*v1.z + v2.z*v2.z),
            sqrtf(EPSV + v0.w*v0.w + v1.w*v1.w + v2.w*v2.w));
    }
}

// ================= fused 2-layer MLP: C[M,384] = silu(A@W1 + b1) @ W2 + b2 =================
#define FS_ASH1 0
#define FS_ASL1 5120
#define FS_BS1  10240
#define FS_HH   20480
#define FS_HL   37888
#define FS_BS2  55296
#define FS_TOTAL 90112

template<int MODE>
__global__ __launch_bounds__(256)
void fused_mlp(const float* __restrict__ A, const float* __restrict__ A2,
               const __half* __restrict__ W1f, const float* __restrict__ b1,
               const __half* __restrict__ W2f, const float* __restrict__ b2,
               float* __restrict__ C, int M, int K1) {
    extern __shared__ char smem[];
    __half (*AsH1)[40]  = (__half(*)[40])(smem + FS_ASH1);
    __half (*AsL1)[40]  = (__half(*)[40])(smem + FS_ASL1);
    __half (*Bs1)[40]   = (__half(*)[40])(smem + FS_BS1);
    __half (*hH)[136]   = (__half(*)[136])(smem + FS_HH);
    __half (*hL)[136]   = (__half(*)[136])(smem + FS_HL);
    __half (*Bs2)[136]  = (__half(*)[136])(smem + FS_BS2);

    int tid = threadIdx.x, wid = tid >> 5, lane = tid & 31;
    int row0 = blockIdx.x * 64;
    int wm = wid >> 2, wn = wid & 3;
    int gID = lane >> 2, tig = lane & 3;

    // ---------- stage 1 ----------
    float acc[2][4][4];
    #pragma unroll
    for (int mt = 0; mt < 2; ++mt)
        #pragma unroll
        for (int nt = 0; nt < 4; ++nt)
            #pragma unroll
            for (int i = 0; i < 4; ++i) acc[mt][nt][i] = 0.f;

    int nc = K1 >> 5;
    float4 ra[2];
    uint4 rb1[2];
    int ar[2], ac[2];
    #pragma unroll
    for (int p = 0; p < 2; ++p) {
        int idx = tid + p * 256;
        ar[p] = idx >> 3; ac[p] = (idx & 7) * 4;
    }
    int bn[2], bk[2];
    #pragma unroll
    for (int p = 0; p < 2; ++p) {
        int idx = tid + p * 256;
        bn[p] = idx >> 2; bk[p] = (idx & 3) * 8;
    }

    #pragma unroll
    for (int p = 0; p < 2; ++p) {
        ra[p] = load_a<MODE>(A, A2, row0 + ar[p], M, K1, ac[p]);
        rb1[p] = *(const uint4*)&W1f[(size_t)bn[p] * K1 + bk[p]];
    }

    for (int c = 0; c < nc; ++c) {
        #pragma unroll
        for (int p = 0; p < 2; ++p) {
            uint2 hh, ll;
            split4_pack(ra[p], hh, ll);
            *(uint2*)&AsH1[ar[p]][ac[p]] = hh;
            *(uint2*)&AsL1[ar[p]][ac[p]] = ll;
            *(uint4*)&Bs1[bn[p]][bk[p]] = rb1[p];
        }
        __syncthreads();

        if (c + 1 < nc) {
            int k0n = (c + 1) << 5;
            #pragma unroll
            for (int p = 0; p < 2; ++p) {
                ra[p] = load_a<MODE>(A, A2, row0 + ar[p], M, K1, k0n + ac[p]);
                rb1[p] = *(const uint4*)&W1f[(size_t)bn[p] * K1 + k0n + bk[p]];
            }
        }

        #pragma unroll
        for (int ks = 0; ks < 32; ks += 16) {
            uint32_t ah[2][4], al[2][4], bf[4][2];
            int cc = ks + tig * 2;
            #pragma unroll
            for (int mt = 0; mt < 2; ++mt) {
                int r = wm * 32 + mt * 16 + gID;
                ah[mt][0] = *(const uint32_t*)&AsH1[r][cc];
                ah[mt][1] = *(const uint32_t*)&AsH1[r + 8][cc];
                ah[mt][2] = *(const uint32_t*)&AsH1[r][cc + 8];
                ah[mt][3] = *(const uint32_t*)&AsH1[r + 8][cc + 8];
                al[mt][0] = *(const uint32_t*)&AsL1[r][cc];
                al[mt][1] = *(const uint32_t*)&AsL1[r + 8][cc];
                al[mt][2] = *(const uint32_t*)&AsL1[r][cc + 8];
                al[mt][3] = *(const uint32_t*)&AsL1[r + 8][cc + 8];
            }
            #pragma unroll
            for (int nt = 0; nt < 4; ++nt) {
                int cr = wn * 32 + nt * 8 + gID;
                bf[nt][0] = *(const uint32_t*)&Bs1[cr][cc];
                bf[nt][1] = *(const uint32_t*)&Bs1[cr][cc + 8];
            }
            #pragma unroll
            for (int mt = 0; mt < 2; ++mt)
                #pragma unroll
                for (int nt = 0; nt < 4; ++nt) {
                    MMA16816F(acc[mt][nt], ah[mt], bf[nt]);
                    MMA16816F(acc[mt][nt], al[mt], bf[nt]);
                }
        }
        __syncthreads();
    }

    // stage-1 epilogue: silu -> hH/hL (vectorized half2 stores)
    #pragma unroll
    for (int mt = 0; mt < 2; ++mt) {
        int r = wm * 32 + mt * 16 + gID;
        #pragma unroll
        for (int nt = 0; nt < 4; ++nt) {
            int c = wn * 32 + nt * 8 + tig * 2;
            float b0 = b1[c], bb1 = b1[c + 1];
            float v00 = silu(acc[mt][nt][0] + b0), v01 = silu(acc[mt][nt][1] + bb1);
            float v10 = silu(acc[mt][nt][2] + b0), v11 = silu(acc[mt][nt][3] + bb1);
            __half h0, l0, h1, l1;
            split_f16(v00, h0, l0); split_f16(v01, h1, l1);
            *(__half2*)&hH[r][c] = __halves2half2(h0, h1);
            *(__half2*)&hL[r][c] = __halves2half2(l0, l1);
            split_f16(v10, h0, l0); split_f16(v11, h1, l1);
            *(__half2*)&hH[r + 8][c] = __halves2half2(h0, h1);
            *(__half2*)&hL[r + 8][c] = __halves2half2(l0, l1);
        }
    }
    __syncthreads();

    // ---------- stage 2 ----------
    for (int ch = 0; ch < 3; ++ch) {
        #pragma unroll
        for (int p = 0; p < 8; ++p) {
            int idx = tid + p * 256;
            int n = idx >> 4, kc = (idx & 15) * 8;
            *(uint4*)&Bs2[n][kc] = *(const uint4*)&W2f[(size_t)(ch * 128 + n) * 128 + kc];
        }
        __syncthreads();

        float acc2[2][4][4];
        #pragma unroll
        for (int mt = 0; mt < 2; ++mt)
            #pragma unroll
            for (int nt = 0; nt < 4; ++nt)
                #pragma unroll
                for (int i = 0; i < 4; ++i) acc2[mt][nt][i] = 0.f;

        #pragma unroll
        for (int ks = 0; ks < 128; ks += 16) {
            uint32_t ah[2][4], al[2][4], bf[4][2];
            int cc = ks + tig * 2;
            #pragma unroll
            for (int mt = 0; mt < 2; ++mt) {
                int r = wm * 32 + mt * 16 + gID;
                ah[mt][0] = *(const uint32_t*)&hH[r][cc];
                ah[mt][1] = *(const uint32_t*)&hH[r + 8][cc];
                ah[mt][2] = *(const uint32_t*)&hH[r][cc + 8];
                ah[mt][3] = *(const uint32_t*)&hH[r + 8][cc + 8];
                al[mt][0] = *(const uint32_t*)&hL[r][cc];
                al[mt][1] = *(const uint32_t*)&hL[r + 8][cc];
                al[mt][2] = *(const uint32_t*)&hL[r][cc + 8];
                al[mt][3] = *(const uint32_t*)&hL[r + 8][cc + 8];
            }
            #pragma unroll
            for (int nt = 0; nt < 4; ++nt) {
                int cr = wn * 32 + nt * 8 + gID;
                bf[nt][0] = *(const uint32_t*)&Bs2[cr][cc];
                bf[nt][1] = *(const uint32_t*)&Bs2[cr][cc + 8];
            }
            #pragma unroll
            for (int mt = 0; mt < 2; ++mt)
                #pragma unroll
                for (int nt = 0; nt < 4; ++nt) {
                    MMA16816F(acc2[mt][nt], ah[mt], bf[nt]);
                    MMA16816F(acc2[mt][nt], al[mt], bf[nt]);
                }
        }

        #pragma unroll
        for (int mt = 0; mt < 2; ++mt) {
            int r = row0 + wm * 32 + mt * 16 + gID;
            #pragma unroll
            for (int nt = 0; nt < 4; ++nt) {
                int c = ch * 128 + wn * 32 + nt * 8 + tig * 2;
                float b0 = b2[c], bb = b2[c + 1];
                if (r < M) {
                    C[(size_t)r * F3 + c]     = acc2[mt][nt][0] + b0;
                    C[(size_t)r * F3 + c + 1] = acc2[mt][nt][1] + bb;
                }
                if (r + 8 < M) {
                    C[(size_t)(r + 8) * F3 + c]     = acc2[mt][nt][2] + b0;
                    C[(size_t)(r + 8) * F3 + c + 1] = acc2[mt][nt][3] + bb;
                }
            }
        }
        if (ch < 2) __syncthreads();
    }
}

// ================= plain GEMM (for mumix): C = A @ W, N=256 =================
template<int MODE>
__global__ __launch_bounds__(256)
void mma_gemm(const float* __restrict__ A, const float* __restrict__ A2,
              const __half* __restrict__ BF, float* __restrict__ C,
              int M, int N, int K) {
    __shared__ __half AsH[128][40], AsL[128][40];
    __shared__ __half Bs[64][40];

    int tid = threadIdx.x, wid = tid >> 5, lane = tid & 31;
    int row0 = blockIdx.y * 128, col0 = blockIdx.x * 64;
    int wm = wid >> 1, wn = wid & 1;
    int gID = lane >> 2, tig = lane & 3;

    float acc[2][4][4];
    #pragma unroll
    for (int mt = 0; mt < 2; ++mt)
        #pragma unroll
        for (int nt = 0; nt < 4; ++nt)
            #pragma unroll
            for (int i = 0; i < 4; ++i) acc[mt][nt][i] = 0.f;

    int nc = K >> 5;
    float4 ra[4];
    uint4 rb;
    int br = tid >> 2, bc = (tid & 3) * 8;
    int arf = tid >> 3, acf = (tid & 7) * 4;

    #pragma unroll
    for (int p = 0; p < 4; ++p)
        ra[p] = load_a<MODE>(A, A2, row0 + arf + p * 32, M, K, acf);
    rb = *(const uint4*)&BF[(size_t)(col0 + br) * K + bc];

    for (int c = 0; c < nc; ++c) {
        #pragma unroll
        for (int p = 0; p < 4; ++p) {
            int r = arf + p * 32;
            uint2 hh, ll;
            split4_pack(ra[p], hh, ll);
            *(uint2*)&AsH[r][acf] = hh;
            *(uint2*)&AsL[r][acf] = ll;
        }
        *(uint4*)&Bs[br][bc] = rb;
        __syncthreads();

        if (c + 1 < nc) {
            int k0n = (c + 1) << 5;
            #pragma unroll
            for (int p = 0; p < 4; ++p)
                ra[p] = load_a<MODE>(A, A2, row0 + arf + p * 32, M, K, k0n + acf);
            rb = *(const uint4*)&BF[(size_t)(col0 + br) * K + k0n + bc];
        }

        #pragma unroll
        for (int ks = 0; ks < 32; ks += 16) {
            uint32_t ah[2][4], al[2][4], bf[4][2];
            int cc = ks + tig * 2;
            #pragma unroll
            for (int mt = 0; mt < 2; ++mt) {
                int r = wm * 32 + mt * 16 + gID;
                ah[mt][0] = *(const uint32_t*)&AsH[r][cc];
                ah[mt][1] = *(const uint32_t*)&AsH[r + 8][cc];
                ah[mt][2] = *(const uint32_t*)&AsH[r][cc + 8];
                ah[mt][3] = *(const uint32_t*)&AsH[r + 8][cc + 8];
                al[mt][0] = *(const uint32_t*)&AsL[r][cc];
                al[mt][1] = *(const uint32_t*)&AsL[r + 8][cc];
                al[mt][2] = *(const uint32_t*)&AsL[r][cc + 8];
                al[mt][3] = *(const uint32_t*)&AsL[r + 8][cc + 8];
            }
            #pragma unroll
            for (int nt = 0; nt < 4; ++nt) {
                int cr = wn * 32 + nt * 8 + gID;
                bf[nt][0] = *(const uint32_t*)&Bs[cr][cc];
                bf[nt][1] = *(const uint32_t*)&Bs[cr][cc + 8];
            }
            #pragma unroll
            for (int mt = 0; mt < 2; ++mt)
                #pragma unroll
                for (int nt = 0; nt < 4; ++nt) {
                    MMA16816F(acc[mt][nt], ah[mt], bf[nt]);
                    MMA16816F(acc[mt][nt], al[mt], bf[nt]);
                }
        }
        __syncthreads();
    }

    #pragma unroll
    for (int mt = 0; mt < 2; ++mt) {
        int r = row0 + wm * 32 + mt * 16 + gID;
        #pragma unroll
        for (int nt = 0; nt < 4; ++nt) {
            int c = col0 + wn * 32 + nt * 8 + tig * 2;
            if (r < M) {
                C[(size_t)r * N + c]     = acc[mt][nt][0];
                C[(size_t)r * N + c + 1] = acc[mt][nt][1];
            }
            if (r + 8 < M) {
                C[(size_t)(r + 8) * N + c]     = acc[mt][nt][2];
                C[(size_t)(r + 8) * N + c + 1] = acc[mt][nt][3];
            }
        }
    }
}

// ---------------- per-edge contribution (full) ----------------
__device__ __forceinline__ void edge_body(const int* __restrict__ idx_j, int e, int t,
                                          float& aq, float& a0, float& a1, float& a2) {
    float4 g = g_geo[e];
    float d = g.w;
    if (d >= CUTOFF) return;
    int j = idx_j[e];

    float u = d * INV_STEP;
    int k = (int)u; if (k > NTAB - 2) k = NTAB - 2;
    float f = u - (float)k;
    const __half2* tp = &g_tab2[(size_t)k * F3];
    float2 p0 = __half22float2(tp[t]);
    float2 p1 = __half22float2(tp[F_DIM + t]);
    float2 p2 = __half22float2(tp[2 * F_DIM + t]);
    float w0 = fmaf(f, p0.y - p0.x, p0.x);
    float w1 = fmaf(f, p1.y - p1.x, p1.x);
    float w2 = fmaf(f, p2.y - p2.x, p2.x);

    const float* xr = &g_x[(size_t)j * F3];
    float xj0 = xr[t], xj1 = xr[F_DIM + t], xj2 = xr[2 * F_DIM + t];
    const float* mr = &g_mu[(size_t)j * 3 * F_DIM];
    float m0 = mr[t], m1 = mr[F_DIM + t], m2 = mr[2 * F_DIM + t];

    aq += w0 * xj0;
    float dmuR  = w1 * xj1;
    float dmumu = w2 * xj2;
    a0 += dmuR * g.x + dmumu * m0;
    a1 += dmuR * g.y + dmumu * m1;
    a2 += dmuR * g.z + dmumu * m2;
}

// ---------------- per-edge contribution, iteration 0 (mu == 0) ----------------
__device__ __forceinline__ void edge_body0(const int* __restrict__ idx_j, int e, int t,
                                           float& aq, float& a0, float& a1, float& a2) {
    float4 g = g_geo[e];
    float d = g.w;
    if (d >= CUTOFF) return;
    int j = idx_j[e];

    float u = d * INV_STEP;
    int k = (int)u; if (k > NTAB - 2) k = NTAB - 2;
    float f = u - (float)k;
    const __half2* tp = &g_tab2[(size_t)k * F3];
    float2 p0 = __half22float2(tp[t]);
    float2 p1 = __half22float2(tp[F_DIM + t]);
    float w0 = fmaf(f, p0.y - p0.x, p0.x);
    float w1 = fmaf(f, p1.y - p1.x, p1.x);

    const float* xr = &g_x[(size_t)j * F3];
    float xj0 = xr[t], xj1 = xr[F_DIM + t];

    aq += w0 * xj0;
    float dmuR = w1 * xj1;
    a0 += dmuR * g.x;
    a1 += dmuR * g.y;
    a2 += dmuR * g.z;
}

__global__ void edge_message_csr(const int* __restrict__ idx_j) {
    int n = blockIdx.x, t = threadIdx.x;
    int e0 = g_row[n], e1 = g_row[n + 1];
    float aq0 = 0.f, x0 = 0.f, y0 = 0.f, z0 = 0.f;
    float aq1 = 0.f, x1 = 0.f, y1 = 0.f, z1 = 0.f;

    int e = e0;
    for (; e + 4 <= e1; e += 4) {
        edge_body(idx_j, e,     t, aq0, x0, y0, z0);
        edge_body(idx_j, e + 1, t, aq1, x1, y1, z1);
        edge_body(idx_j, e + 2, t, aq0, x0, y0, z0);
        edge_body(idx_j, e + 3, t, aq1, x1, y1, z1);
    }
    for (; e < e1; ++e) edge_body(idx_j, e, t, aq0, x0, y0, z0);

    g_q[n * F_DIM + t] += aq0 + aq1;
    g_dmu[(n * 3 + 0) * F_DIM + t] = x0 + x1;
    g_dmu[(n * 3 + 1) * F_DIM + t] = y0 + y1;
    g_dmu[(n * 3 + 2) * F_DIM + t] = z0 + z1;
}

__global__ void edge_message_csr0(const int* __restrict__ idx_j) {
    int n = blockIdx.x, t = threadIdx.x;
    int e0 = g_row[n], e1 = g_row[n + 1];
    float aq0 = 0.f, x0 = 0.f, y0 = 0.f, z0 = 0.f;
    float aq1 = 0.f, x1 = 0.f, y1 = 0.f, z1 = 0.f;

    int e = e0;
    for (; e + 4 <= e1; e += 4) {
        edge_body0(idx_j, e,     t, aq0, x0, y0, z0);
        edge_body0(idx_j, e + 1, t, aq1, x1, y1, z1);
        edge_body0(idx_j, e + 2, t, aq0, x0, y0, z0);
        edge_body0(idx_j, e + 3, t, aq1, x1, y1, z1);
    }
    for (; e < e1; ++e) edge_body0(idx_j, e, t, aq0, x0, y0, z0);

    g_q[n * F_DIM + t] += aq0 + aq1;
    g_dmu[(n * 3 + 0) * F_DIM + t] = x0 + x1;
    g_dmu[(n * 3 + 1) * F_DIM + t] = y0 + y1;
    g_dmu[(n * 3 + 2) * F_DIM + t] = z0 + z1;
}

// ---------------- mixing update ----------------
__global__ void mix_update() {
    int n = blockIdx.x, t = threadIdx.x;
    float dq   = g_xm[n * F3 + t];
    float dmu  = g_xm[n * F3 + F_DIM + t];
    float dqmu = g_xm[n * F3 + 2 * F_DIM + t];
    float s = 0.f;
    #pragma unroll
    for (int a = 0; a < 3; ++a) {
        float v = g_mumix[(n * 3 + a) * (2 * F_DIM) + t];
        float w = g_mumix[(n * 3 + a) * (2 * F_DIM) + F_DIM + t];
        s += v * w;
        g_mu[(n * 3 + a) * F_DIM + t] += g_dmu[(n * 3 + a) * F_DIM + t] + dmu * w;
    }
    g_q[n * F_DIM + t] += dq + dqmu * s;
}

// ================= host launch =================
extern "C" void kernel_launch(void* const* d_in, const int* in_sizes, int n_in,
                              void* d_out, int out_size) {
    (void)in_sizes; (void)n_in; (void)out_size;
    const int*   Z       = (const int*)  d_in[0];
    const float* R       = (const float*)d_in[1];
    const int*   idx_i   = (const int*)  d_in[2];
    const int*   idx_j   = (const int*)  d_in[3];
    const float* offs    = (const float*)d_in[4];
    const float* emb     = (const float*)d_in[5];
    const float* filt_W  = (const float*)d_in[6];
    const float* filt_b  = (const float*)d_in[7];
    const float* int_W1  = (const float*)d_in[8];
    const float* int_b1  = (const float*)d_in[9];
    const float* int_W2  = (const float*)d_in[10];
    const float* int_b2  = (const float*)d_in[11];
    const float* mix_Wmu = (const float*)d_in[12];
    const float* mix_W1  = (const float*)d_in[13];
    const float* mix_b1  = (const float*)d_in[14];
    const float* mix_W2  = (const float*)d_in[15];
    const float* mix_b2  = (const float*)d_in[16];
    float* out = (float*)d_out;

    void *p_q, *p_mu, *p_x, *p_dmu, *p_mumix, *p_xm, *p_wF;
    cudaGetSymbolAddress(&p_q, g_q);
    cudaGetSymbolAddress(&p_mu, g_mu);
    cudaGetSymbolAddress(&p_x, g_x);
    cudaGetSymbolAddress(&p_dmu, g_dmu);
    cudaGetSymbolAddress(&p_mumix, g_mumix);
    cudaGetSymbolAddress(&p_xm, g_xm);
    cudaGetSymbolAddress(&p_wF, g_wF);

    cudaFuncSetAttribute(fused_mlp<0>, cudaFuncAttributeMaxDynamicSharedMemorySize, FS_TOTAL);
    cudaFuncSetAttribute(fused_mlp<2>, cudaFuncAttributeMaxDynamicSharedMemorySize, FS_TOTAL);

    fused_pre<<<NB_PRE, 384>>>(R, idx_i, idx_j, offs, filt_W, filt_b, Z, emb,
                               int_W1, int_W2, mix_Wmu, mix_W1, mix_W2);

    const __half* wF = (const __half*)p_wF;
    const int NBLK = (N_ATOMS + 63) / 64;     // 157

    for (int it = 0; it < 3; ++it) {
        size_t wb = (size_t)it * WT_PER_ITER;

        fused_mlp<0><<<NBLK, 256, FS_TOTAL>>>(
            (const float*)p_q, nullptr,
            wF + wb + 0, int_b1 + (long)it * F_DIM,
            wF + wb + 16384, int_b2 + (long)it * F3,
            (float*)p_x, N_ATOMS, F_DIM);

        if (it == 0) edge_message_csr0<<<N_ATOMS, 128>>>(idx_j);
        else         edge_message_csr <<<N_ATOMS, 128>>>(idx_j);

        if (it == 0)
            mma_gemm<0><<<dim3(4, 235), 256>>>(
                (const float*)p_dmu, nullptr, wF + wb + 65536,
                (float*)p_mumix, 3 * N_ATOMS, 2 * F_DIM, F_DIM);
        else
            mma_gemm<1><<<dim3(4, 235), 256>>>(
                (const float*)p_mu, (const float*)p_dmu, wF + wb + 65536,
                (float*)p_mumix, 3 * N_ATOMS, 2 * F_DIM, F_DIM);

        fused_mlp<2><<<NBLK, 256, FS_TOTAL>>>(
            (const float*)p_q, (const float*)p_mumix,
            wF + wb + 98304, mix_b1 + (long)it * F_DIM,
            wF + wb + 131072, mix_b2 + (long)it * F3,
            (float*)p_xm, N_ATOMS, 2 * F_DIM);

        mix_update<<<N_ATOMS, 128>>>();
    }

    cudaMemcpyAsync(out, p_q, (size_t)N_ATOMS * F_DIM * sizeof(float),
                    cudaMemcpyDeviceToDevice);
    cudaMemcpyAsync(out + (size_t)N_ATOMS * F_DIM, p_mu,
                    (size_t)N_ATOMS * 3 * F_DIM * sizeof(float),
                    cudaMemcpyDeviceToDevice);
}

// round 16
// speedup vs baseline: 1.4322x; 1.0615x over previous
#include <cuda_runtime.h>
#include <cuda_bf16.h>
#include <cuda_fp16.h>
#include <math.h>
#include <stdint.h>

#define N_ATOMS 10000
#define N_EDGES 250000
#define F_DIM   128
#define F3      384
#define N_RBF   20
#define CUTOFF  5.0f
#define EPSV    1e-8f
#define NTAB    8192
#define INV_STEP ((float)(NTAB - 1) / CUTOFF)
#define WT_PER_ITER 180224   // 16384+49152+32768+32768+49152

// ---------------- scratch (device globals; no allocation allowed) ----------------
__device__ __half2 g_tab2[(size_t)NTAB * F3];
__device__ float4 g_geo [N_EDGES];
__device__ int    g_row [N_ATOMS + 1];
__device__ float g_q   [N_ATOMS * F_DIM];
__device__ float g_mu  [N_ATOMS * 3 * F_DIM];
__device__ float g_x   [N_ATOMS * F3];
__device__ float g_dmu [N_ATOMS * 3 * F_DIM];
__device__ float g_mumix[N_ATOMS * 3 * 2 * F_DIM];
__device__ float g_xm  [N_ATOMS * F3];
__device__ __half g_wF[3 * WT_PER_ITER];

__device__ __forceinline__ void split_f16(float v, __half& h, __half& l) {
    h = __float2half(v);
    l = __float2half(v - __half2float(h));
}
__device__ __forceinline__ float silu(float v) { return v / (1.0f + expf(-v)); }

__device__ __forceinline__ void split4_pack(float4 v, uint2& hh, uint2& ll) {
    __half hx, lx, hy, ly, hz, lz, hw, lw;
    split_f16(v.x, hx, lx); split_f16(v.y, hy, ly);
    split_f16(v.z, hz, lz); split_f16(v.w, hw, lw);
    __half2 h01 = __halves2half2(hx, hy), h23 = __halves2half2(hz, hw);
    __half2 l01 = __halves2half2(lx, ly), l23 = __halves2half2(lz, lw);
    hh.x = *(uint32_t*)&h01; hh.y = *(uint32_t*)&h23;
    ll.x = *(uint32_t*)&l01; ll.y = *(uint32_t*)&l23;
}

#define MMA16816F(d, a, b) \
    asm volatile("mma.sync.aligned.m16n8k16.row.col.f32.f16.f16.f32 " \
        "{%0,%1,%2,%3}, {%4,%5,%6,%7}, {%8,%9}, {%0,%1,%2,%3};" \
        : "+f"((d)[0]), "+f"((d)[1]), "+f"((d)[2]), "+f"((d)[3]) \
        : "r"((a)[0]), "r"((a)[1]), "r"((a)[2]), "r"((a)[3]), \
          "r"((b)[0]), "r"((b)[1]))

// ================= fused precompute mega-kernel =================
#define NB_GEO ((N_EDGES + 383) / 384)
#define NB_ROW ((N_ATOMS + 384) / 384)
#define NB_PRE (NTAB + N_ATOMS + 2880 + NB_GEO + NB_ROW)

__global__ __launch_bounds__(384)
void fused_pre(const float* __restrict__ R,
               const int* __restrict__ idx_i, const int* __restrict__ idx_j,
               const float* __restrict__ offs,
               const float* __restrict__ filt_W, const float* __restrict__ filt_b,
               const int* __restrict__ Z, const float* __restrict__ emb,
               const float* __restrict__ W1, const float* __restrict__ W2,
               const float* __restrict__ Wmu, const float* __restrict__ M1,
               const float* __restrict__ M2) {
    int b = blockIdx.x, t = threadIdx.x;

    if (b < NTAB) {
        int k = b, c = t;
        __shared__ float s_phi[2][N_RBF];
        const float step = CUTOFF / (float)(NTAB - 1);
        float d0 = (float)k * step;
        int k1 = (k + 1 < NTAB) ? k + 1 : k;
        float d1 = (float)k1 * step;
        if (c < N_RBF) {
            const float spacing = CUTOFF / (float)(N_RBF - 1);
            const float coeff = -0.5f / (spacing * spacing);
            float dd0 = d0 - (float)c * spacing;
            float dd1 = d1 - (float)c * spacing;
            s_phi[0][c] = expf(coeff * dd0 * dd0);
            s_phi[1][c] = expf(coeff * dd1 * dd1);
        }
        __syncthreads();
        float fc0 = (d0 < CUTOFF) ? 0.5f * (cosf(d0 * (float)(M_PI / 5.0)) + 1.0f) : 0.0f;
        float fc1 = (d1 < CUTOFF) ? 0.5f * (cosf(d1 * (float)(M_PI / 5.0)) + 1.0f) : 0.0f;
        float a0 = filt_b[c], a1 = filt_b[c];
        #pragma unroll
        for (int r = 0; r < N_RBF; ++r) {
            float w = filt_W[r * F3 + c];
            a0 += s_phi[0][r] * w;
            a1 += s_phi[1][r] * w;
        }
        g_tab2[(size_t)k * F3 + c] = __floats2half2_rn(a0 * fc0, a1 * fc1);
        return;
    }
    b -= NTAB;

    if (b < N_ATOMS) {
        if (t < F_DIM) {
            int z = Z[b];
            g_q[b * F_DIM + t] = emb[z * F_DIM + t];
            #pragma unroll
            for (int a = 0; a < 3; ++a)
                g_mu[(b * 3 + a) * F_DIM + t] = 0.0f;
        }
        return;
    }
    b -= N_ATOMS;

    if (b < 2880) {
        if (t >= 256) return;
        const int Ks[5]  = {128, 128, 128, 256, 128};
        const int Ns[5]  = {128, 384, 256, 128, 384};
        const int off[5] = {0, 16384, 65536, 98304, 131072};
        int m = b / 192;
        int local = b % 192;
        int it = m / 5, s = m % 5;
        int K = Ks[s], N = Ns[s];
        int idx = local * 256 + t;
        if (idx >= K * N) return;
        const float* src;
        switch (s) {
            case 0: src = W1  + (size_t)it * 16384; break;
            case 1: src = W2  + (size_t)it * 49152; break;
            case 2: src = Wmu + (size_t)it * 32768; break;
            case 3: src = M1  + (size_t)it * 32768; break;
            default: src = M2 + (size_t)it * 49152; break;
        }
        int k = idx / N, n = idx % N;
        g_wF[(size_t)it * WT_PER_ITER + off[s] + (size_t)n * K + k] = __float2half(src[idx]);
        return;
    }
    b -= 2880;

    if (b < NB_GEO) {
        int e = b * 384 + t;
        if (e >= N_EDGES) return;
        int i = idx_i[e], j = idx_j[e];
        float rx = R[j*3+0] - R[i*3+0] + offs[e*3+0];
        float ry = R[j*3+1] - R[i*3+1] + offs[e*3+1];
        float rz = R[j*3+2] - R[i*3+2] + offs[e*3+2];
        float d = sqrtf(rx*rx + ry*ry + rz*rz);
        float inv = 1.0f / d;
        g_geo[e] = make_float4(rx*inv, ry*inv, rz*inv, d);
        return;
    }
    b -= NB_GEO;

    {
        int n = b * 384 + t;
        if (n > N_ATOMS) return;
        int lo = 0, hi = N_EDGES;
        while (lo < hi) {
            int mid = (lo + hi) >> 1;
            if (idx_i[mid] < n) lo = mid + 1; else hi = mid;
        }
        g_row[n] = lo;
    }
}

// ================= A-tile loader (compile-time MODE) =================
template<int MODE>
__device__ __forceinline__ float4 load_a(const float* __restrict__ A,
                                         const float* __restrict__ A2,
                                         int gr, int M, int K, int kcol) {
    if (gr >= M) return make_float4(0.f, 0.f, 0.f, 0.f);
    if (MODE == 0) {
        return *(const float4*)&A[(size_t)gr * K + kcol];
    } else if (MODE == 1) {
        float4 a = *(const float4*)&A[(size_t)gr * K + kcol];
        float4 b = *(const float4*)&A2[(size_t)gr * K + kcol];
        return make_float4(a.x + b.x, a.y + b.y, a.z + b.z, a.w + b.w);
    } else {
        if (kcol < 128) return *(const float4*)&A[(size_t)gr * 128 + kcol];
        int c = kcol - 128;
        float4 v0 = *(const float4*)&A2[((size_t)gr * 3 + 0) * 256 + c];
        float4 v1 = *(const float4*)&A2[((size_t)gr * 3 + 1) * 256 + c];
        float4 v2 = *(const float4*)&A2[((size_t)gr * 3 + 2) * 256 + c];
        return make_float4(
            sqrtf(EPSV + v0.x*v0.x + v1.x*v1.x + v2.x*v2.x),
            sqrtf(EPSV + v0.y*v0.y + v1.y*v1.y + v2.y*v2.y),
            sqrtf(EPSV + v0.z*v0.z + v1.z*v1.z + v2.z*v2.z),
            sqrtf(EPSV + v0.w*v0.w + v1.w*v1.w + v2.w*v2.w));
    }
}

// ================= fused 2-layer MLP =================
#define FS_ASH1 0
#define FS_ASL1 5120
#define FS_BS1  10240
#define FS_HH   20480
#define FS_HL   37888
#define FS_BS2  55296
#define FS_TOTAL 90112

template<int MODE>
__global__ __launch_bounds__(256)
void fused_mlp(const float* __restrict__ A, const float* __restrict__ A2,
               const __half* __restrict__ W1f, const float* __restrict__ b1,
               const __half* __restrict__ W2f, const float* __restrict__ b2,
               float* __restrict__ C, int M, int K1) {
    extern __shared__ char smem[];
    __half (*AsH1)[40]  = (__half(*)[40])(smem + FS_ASH1);
    __half (*AsL1)[40]  = (__half(*)[40])(smem + FS_ASL1);
    __half (*Bs1)[40]   = (__half(*)[40])(smem + FS_BS1);
    __half (*hH)[136]   = (__half(*)[136])(smem + FS_HH);
    __half (*hL)[136]   = (__half(*)[136])(smem + FS_HL);
    __half (*Bs2)[136]  = (__half(*)[136])(smem + FS_BS2);

    int tid = threadIdx.x, wid = tid >> 5, lane = tid & 31;
    int row0 = blockIdx.x * 64;
    int wm = wid >> 2, wn = wid & 3;
    int gID = lane >> 2, tig = lane & 3;

    float acc[2][4][4];
    #pragma unroll
    for (int mt = 0; mt < 2; ++mt)
        #pragma unroll
        for (int nt = 0; nt < 4; ++nt)
            #pragma unroll
            for (int i = 0; i < 4; ++i) acc[mt][nt][i] = 0.f;

    int nc = K1 >> 5;
    float4 ra[2];
    uint4 rb1[2];
    int ar[2], ac[2];
    #pragma unroll
    for (int p = 0; p < 2; ++p) {
        int idx = tid + p * 256;
        ar[p] = idx >> 3; ac[p] = (idx & 7) * 4;
    }
    int bn[2], bk[2];
    #pragma unroll
    for (int p = 0; p < 2; ++p) {
        int idx = tid + p * 256;
        bn[p] = idx >> 2; bk[p] = (idx & 3) * 8;
    }

    #pragma unroll
    for (int p = 0; p < 2; ++p) {
        ra[p] = load_a<MODE>(A, A2, row0 + ar[p], M, K1, ac[p]);
        rb1[p] = *(const uint4*)&W1f[(size_t)bn[p] * K1 + bk[p]];
    }

    for (int c = 0; c < nc; ++c) {
        #pragma unroll
        for (int p = 0; p < 2; ++p) {
            uint2 hh, ll;
            split4_pack(ra[p], hh, ll);
            *(uint2*)&AsH1[ar[p]][ac[p]] = hh;
            *(uint2*)&AsL1[ar[p]][ac[p]] = ll;
            *(uint4*)&Bs1[bn[p]][bk[p]] = rb1[p];
        }
        __syncthreads();

        if (c + 1 < nc) {
            int k0n = (c + 1) << 5;
            #pragma unroll
            for (int p = 0; p < 2; ++p) {
                ra[p] = load_a<MODE>(A, A2, row0 + ar[p], M, K1, k0n + ac[p]);
                rb1[p] = *(const uint4*)&W1f[(size_t)bn[p] * K1 + k0n + bk[p]];
            }
        }

        #pragma unroll
        for (int ks = 0; ks < 32; ks += 16) {
            uint32_t ah[2][4], al[2][4], bf[4][2];
            int cc = ks + tig * 2;
            #pragma unroll
            for (int mt = 0; mt < 2; ++mt) {
                int r = wm * 32 + mt * 16 + gID;
                ah[mt][0] = *(const uint32_t*)&AsH1[r][cc];
                ah[mt][1] = *(const uint32_t*)&AsH1[r + 8][cc];
                ah[mt][2] = *(const uint32_t*)&AsH1[r][cc + 8];
                ah[mt][3] = *(const uint32_t*)&AsH1[r + 8][cc + 8];
                al[mt][0] = *(const uint32_t*)&AsL1[r][cc];
                al[mt][1] = *(const uint32_t*)&AsL1[r + 8][cc];
                al[mt][2] = *(const uint32_t*)&AsL1[r][cc + 8];
                al[mt][3] = *(const uint32_t*)&AsL1[r + 8][cc + 8];
            }
            #pragma unroll
            for (int nt = 0; nt < 4; ++nt) {
                int cr = wn * 32 + nt * 8 + gID;
                bf[nt][0] = *(const uint32_t*)&Bs1[cr][cc];
                bf[nt][1] = *(const uint32_t*)&Bs1[cr][cc + 8];
            }
            #pragma unroll
            for (int mt = 0; mt < 2; ++mt)
                #pragma unroll
                for (int nt = 0; nt < 4; ++nt) {
                    MMA16816F(acc[mt][nt], ah[mt], bf[nt]);
                    MMA16816F(acc[mt][nt], al[mt], bf[nt]);
                }
        }
        __syncthreads();
    }

    #pragma unroll
    for (int mt = 0; mt < 2; ++mt) {
        int r = wm * 32 + mt * 16 + gID;
        #pragma unroll
        for (int nt = 0; nt < 4; ++nt) {
            int c = wn * 32 + nt * 8 + tig * 2;
            float b0 = b1[c], bb1 = b1[c + 1];
            float v00 = silu(acc[mt][nt][0] + b0), v01 = silu(acc[mt][nt][1] + bb1);
            float v10 = silu(acc[mt][nt][2] + b0), v11 = silu(acc[mt][nt][3] + bb1);
            __half h0, l0, h1, l1;
            split_f16(v00, h0, l0); split_f16(v01, h1, l1);
            *(__half2*)&hH[r][c] = __halves2half2(h0, h1);
            *(__half2*)&hL[r][c] = __halves2half2(l0, l1);
            split_f16(v10, h0, l0); split_f16(v11, h1, l1);
            *(__half2*)&hH[r + 8][c] = __halves2half2(h0, h1);
            *(__half2*)&hL[r + 8][c] = __halves2half2(l0, l1);
        }
    }
    __syncthreads();

    for (int ch = 0; ch < 3; ++ch) {
        #pragma unroll
        for (int p = 0; p < 8; ++p) {
            int idx = tid + p * 256;
            int n = idx >> 4, kc = (idx & 15) * 8;
            *(uint4*)&Bs2[n][kc] = *(const uint4*)&W2f[(size_t)(ch * 128 + n) * 128 + kc];
        }
        __syncthreads();

        float acc2[2][4][4];
        #pragma unroll
        for (int mt = 0; mt < 2; ++mt)
            #pragma unroll
            for (int nt = 0; nt < 4; ++nt)
                #pragma unroll
                for (int i = 0; i < 4; ++i) acc2[mt][nt][i] = 0.f;

        #pragma unroll
        for (int ks = 0; ks < 128; ks += 16) {
            uint32_t ah[2][4], al[2][4], bf[4][2];
            int cc = ks + tig * 2;
            #pragma unroll
            for (int mt = 0; mt < 2; ++mt) {
                int r = wm * 32 + mt * 16 + gID;
                ah[mt][0] = *(const uint32_t*)&hH[r][cc];
                ah[mt][1] = *(const uint32_t*)&hH[r + 8][cc];
                ah[mt][2] = *(const uint32_t*)&hH[r][cc + 8];
                ah[mt][3] = *(const uint32_t*)&hH[r + 8][cc + 8];
                al[mt][0] = *(const uint32_t*)&hL[r][cc];
                al[mt][1] = *(const uint32_t*)&hL[r + 8][cc];
                al[mt][2] = *(const uint32_t*)&hL[r][cc + 8];
                al[mt][3] = *(const uint32_t*)&hL[r + 8][cc + 8];
            }
            #pragma unroll
            for (int nt = 0; nt < 4; ++nt) {
                int cr = wn * 32 + nt * 8 + gID;
                bf[nt][0] = *(const uint32_t*)&Bs2[cr][cc];
                bf[nt][1] = *(const uint32_t*)&Bs2[cr][cc + 8];
            }
            #pragma unroll
            for (int mt = 0; mt < 2; ++mt)
                #pragma unroll
                for (int nt = 0; nt < 4; ++nt) {
                    MMA16816F(acc2[mt][nt], ah[mt], bf[nt]);
                    MMA16816F(acc2[mt][nt], al[mt], bf[nt]);
                }
        }

        #pragma unroll
        for (int mt = 0; mt < 2; ++mt) {
            int r = row0 + wm * 32 + mt * 16 + gID;
            #pragma unroll
            for (int nt = 0; nt < 4; ++nt) {
                int c = ch * 128 + wn * 32 + nt * 8 + tig * 2;
                float b0 = b2[c], bb = b2[c + 1];
                if (r < M) {
                    C[(size_t)r * F3 + c]     = acc2[mt][nt][0] + b0;
                    C[(size_t)r * F3 + c + 1] = acc2[mt][nt][1] + bb;
                }
                if (r + 8 < M) {
                    C[(size_t)(r + 8) * F3 + c]     = acc2[mt][nt][2] + b0;
                    C[(size_t)(r + 8) * F3 + c + 1] = acc2[mt][nt][3] + bb;
                }
            }
        }
        if (ch < 2) __syncthreads();
    }
}

// ================= plain GEMM (for mumix) =================
template<int MODE>
__global__ __launch_bounds__(256)
void mma_gemm(const float* __restrict__ A, const float* __restrict__ A2,
              const __half* __restrict__ BF, float* __restrict__ C,
              int M, int N, int K) {
    __shared__ __half AsH[128][40], AsL[128][40];
    __shared__ __half Bs[64][40];

    int tid = threadIdx.x, wid = tid >> 5, lane = tid & 31;
    int row0 = blockIdx.y * 128, col0 = blockIdx.x * 64;
    int wm = wid >> 1, wn = wid & 1;
    int gID = lane >> 2, tig = lane & 3;

    float acc[2][4][4];
    #pragma unroll
    for (int mt = 0; mt < 2; ++mt)
        #pragma unroll
        for (int nt = 0; nt < 4; ++nt)
            #pragma unroll
            for (int i = 0; i < 4; ++i) acc[mt][nt][i] = 0.f;

    int nc = K >> 5;
    float4 ra[4];
    uint4 rb;
    int br = tid >> 2, bc = (tid & 3) * 8;
    int arf = tid >> 3, acf = (tid & 7) * 4;

    #pragma unroll
    for (int p = 0; p < 4; ++p)
        ra[p] = load_a<MODE>(A, A2, row0 + arf + p * 32, M, K, acf);
    rb = *(const uint4*)&BF[(size_t)(col0 + br) * K + bc];

    for (int c = 0; c < nc; ++c) {
        #pragma unroll
        for (int p = 0; p < 4; ++p) {
            int r = arf + p * 32;
            uint2 hh, ll;
            split4_pack(ra[p], hh, ll);
            *(uint2*)&AsH[r][acf] = hh;
            *(uint2*)&AsL[r][acf] = ll;
        }
        *(uint4*)&Bs[br][bc] = rb;
        __syncthreads();

        if (c + 1 < nc) {
            int k0n = (c + 1) << 5;
            #pragma unroll
            for (int p = 0; p < 4; ++p)
                ra[p] = load_a<MODE>(A, A2, row0 + arf + p * 32, M, K, k0n + acf);
            rb = *(const uint4*)&BF[(size_t)(col0 + br) * K + k0n + bc];
        }

        #pragma unroll
        for (int ks = 0; ks < 32; ks += 16) {
            uint32_t ah[2][4], al[2][4], bf[4][2];
            int cc = ks + tig * 2;
            #pragma unroll
            for (int mt = 0; mt < 2; ++mt) {
                int r = wm * 32 + mt * 16 + gID;
                ah[mt][0] = *(const uint32_t*)&AsH[r][cc];
                ah[mt][1] = *(const uint32_t*)&AsH[r + 8][cc];
                ah[mt][2] = *(const uint32_t*)&AsH[r][cc + 8];
                ah[mt][3] = *(const uint32_t*)&AsH[r + 8][cc + 8];
                al[mt][0] = *(const uint32_t*)&AsL[r][cc];
                al[mt][1] = *(const uint32_t*)&AsL[r + 8][cc];
                al[mt][2] = *(const uint32_t*)&AsL[r][cc + 8];
                al[mt][3] = *(const uint32_t*)&AsL[r + 8][cc + 8];
            }
            #pragma unroll
            for (int nt = 0; nt < 4; ++nt) {
                int cr = wn * 32 + nt * 8 + gID;
                bf[nt][0] = *(const uint32_t*)&Bs[cr][cc];
                bf[nt][1] = *(const uint32_t*)&Bs[cr][cc + 8];
            }
            #pragma unroll
            for (int mt = 0; mt < 2; ++mt)
                #pragma unroll
                for (int nt = 0; nt < 4; ++nt) {
                    MMA16816F(acc[mt][nt], ah[mt], bf[nt]);
                    MMA16816F(acc[mt][nt], al[mt], bf[nt]);
                }
        }
        __syncthreads();
    }

    #pragma unroll
    for (int mt = 0; mt < 2; ++mt) {
        int r = row0 + wm * 32 + mt * 16 + gID;
        #pragma unroll
        for (int nt = 0; nt < 4; ++nt) {
            int c = col0 + wn * 32 + nt * 8 + tig * 2;
            if (r < M) {
                C[(size_t)r * N + c]     = acc[mt][nt][0];
                C[(size_t)r * N + c + 1] = acc[mt][nt][1];
            }
            if (r + 8 < M) {
                C[(size_t)(r + 8) * N + c]     = acc[mt][nt][2];
                C[(size_t)(r + 8) * N + c + 1] = acc[mt][nt][3];
            }
        }
    }
}

// ---------------- per-edge contribution, 2 features/thread (full) ----------------
__device__ __forceinline__ void edge_body(const int* __restrict__ idx_j, int e, int ft,
                                          float2& aq, float2& a0, float2& a1, float2& a2) {
    float4 g = g_geo[e];
    float d = g.w;
    if (d >= CUTOFF) return;
    int j = idx_j[e];

    float u = d * INV_STEP;
    int k = (int)u; if (k > NTAB - 2) k = NTAB - 2;
    float f = u - (float)k;
    const __half2* tp = &g_tab2[(size_t)k * F3];
    uint2 t0 = *(const uint2*)&tp[ft];
    uint2 t1 = *(const uint2*)&tp[F_DIM + ft];
    uint2 t2 = *(const uint2*)&tp[2 * F_DIM + ft];
    float2 p0a = __half22float2(*(__half2*)&t0.x), p0b = __half22float2(*(__half2*)&t0.y);
    float2 p1a = __half22float2(*(__half2*)&t1.x), p1b = __half22float2(*(__half2*)&t1.y);
    float2 p2a = __half22float2(*(__half2*)&t2.x), p2b = __half22float2(*(__half2*)&t2.y);
    float w0x = fmaf(f, p0a.y - p0a.x, p0a.x), w0y = fmaf(f, p0b.y - p0b.x, p0b.x);
    float w1x = fmaf(f, p1a.y - p1a.x, p1a.x), w1y = fmaf(f, p1b.y - p1b.x, p1b.x);
    float w2x = fmaf(f, p2a.y - p2a.x, p2a.x), w2y = fmaf(f, p2b.y - p2b.x, p2b.x);

    const float* xr = &g_x[(size_t)j * F3];
    float2 xj0 = *(const float2*)&xr[ft];
    float2 xj1 = *(const float2*)&xr[F_DIM + ft];
    float2 xj2 = *(const float2*)&xr[2 * F_DIM + ft];
    const float* mr = &g_mu[(size_t)j * 3 * F_DIM];
    float2 m0 = *(const float2*)&mr[ft];
    float2 m1 = *(const float2*)&mr[F_DIM + ft];
    float2 m2 = *(const float2*)&mr[2 * F_DIM + ft];

    aq.x += w0x * xj0.x;             aq.y += w0y * xj0.y;
    float dRx = w1x * xj1.x,         dRy = w1y * xj1.y;
    float dMx = w2x * xj2.x,         dMy = w2y * xj2.y;
    a0.x += dRx * g.x + dMx * m0.x;  a0.y += dRy * g.x + dMy * m0.y;
    a1.x += dRx * g.y + dMx * m1.x;  a1.y += dRy * g.y + dMy * m1.y;
    a2.x += dRx * g.z + dMx * m2.x;  a2.y += dRy * g.z + dMy * m2.y;
}

// ---------------- per-edge contribution, iteration 0 (mu == 0) ----------------
__device__ __forceinline__ void edge_body0(const int* __restrict__ idx_j, int e, int ft,
                                           float2& aq, float2& a0, float2& a1, float2& a2) {
    float4 g = g_geo[e];
    float d = g.w;
    if (d >= CUTOFF) return;
    int j = idx_j[e];

    float u = d * INV_STEP;
    int k = (int)u; if (k > NTAB - 2) k = NTAB - 2;
    float f = u - (float)k;
    const __half2* tp = &g_tab2[(size_t)k * F3];
    uint2 t0 = *(const uint2*)&tp[ft];
    uint2 t1 = *(const uint2*)&tp[F_DIM + ft];
    float2 p0a = __half22float2(*(__half2*)&t0.x), p0b = __half22float2(*(__half2*)&t0.y);
    float2 p1a = __half22float2(*(__half2*)&t1.x), p1b = __half22float2(*(__half2*)&t1.y);
    float w0x = fmaf(f, p0a.y - p0a.x, p0a.x), w0y = fmaf(f, p0b.y - p0b.x, p0b.x);
    float w1x = fmaf(f, p1a.y - p1a.x, p1a.x), w1y = fmaf(f, p1b.y - p1b.x, p1b.x);

    const float* xr = &g_x[(size_t)j * F3];
    float2 xj0 = *(const float2*)&xr[ft];
    float2 xj1 = *(const float2*)&xr[F_DIM + ft];

    aq.x += w0x * xj0.x;     aq.y += w0y * xj0.y;
    float dRx = w1x * xj1.x, dRy = w1y * xj1.y;
    a0.x += dRx * g.x;       a0.y += dRy * g.x;
    a1.x += dRx * g.y;       a1.y += dRy * g.y;
    a2.x += dRx * g.z;       a2.y += dRy * g.z;
}

#define EDGE_EPILOG()                                                   \
    do {                                                                \
        float2 qv = *(float2*)&g_q[n * F_DIM + ft];                     \
        qv.x += aq0.x + aq1.x; qv.y += aq0.y + aq1.y;                   \
        *(float2*)&g_q[n * F_DIM + ft] = qv;                            \
        *(float2*)&g_dmu[(n * 3 + 0) * F_DIM + ft] =                    \
            make_float2(x0.x + x1.x, x0.y + x1.y);                      \
        *(float2*)&g_dmu[(n * 3 + 1) * F_DIM + ft] =                    \
            make_float2(y0.x + y1.x, y0.y + y1.y);                      \
        *(float2*)&g_dmu[(n * 3 + 2) * F_DIM + ft] =                    \
            make_float2(z0.x + z1.x, z0.y + z1.y);                      \
    } while (0)

// ---------------- CSR edge message pass: one block (64 thr) per atom, unroll-4 ----------------
__global__ __launch_bounds__(64)
void edge_message_csr(const int* __restrict__ idx_j) {
    int n = blockIdx.x, ft = threadIdx.x * 2;
    int e0 = g_row[n], e1 = g_row[n + 1];
    float2 aq0 = {0,0}, x0 = {0,0}, y0 = {0,0}, z0 = {0,0};
    float2 aq1 = {0,0}, x1 = {0,0}, y1 = {0,0}, z1 = {0,0};

    int e = e0;
    for (; e + 4 <= e1; e += 4) {
        edge_body(idx_j, e,     ft, aq0, x0, y0, z0);
        edge_body(idx_j, e + 1, ft, aq1, x1, y1, z1);
        edge_body(idx_j, e + 2, ft, aq0, x0, y0, z0);
        edge_body(idx_j, e + 3, ft, aq1, x1, y1, z1);
    }
    for (; e < e1; ++e) edge_body(idx_j, e, ft, aq0, x0, y0, z0);

    EDGE_EPILOG();
}

__global__ __launch_bounds__(64)
void edge_message_csr0(const int* __restrict__ idx_j) {
    int n = blockIdx.x, ft = threadIdx.x * 2;
    int e0 = g_row[n], e1 = g_row[n + 1];
    float2 aq0 = {0,0}, x0 = {0,0}, y0 = {0,0}, z0 = {0,0};
    float2 aq1 = {0,0}, x1 = {0,0}, y1 = {0,0}, z1 = {0,0};

    int e = e0;
    for (; e + 4 <= e1; e += 4) {
        edge_body0(idx_j, e,     ft, aq0, x0, y0, z0);
        edge_body0(idx_j, e + 1, ft, aq1, x1, y1, z1);
        edge_body0(idx_j, e + 2, ft, aq0, x0, y0, z0);
        edge_body0(idx_j, e + 3, ft, aq1, x1, y1, z1);
    }
    for (; e < e1; ++e) edge_body0(idx_j, e, ft, aq0, x0, y0, z0);

    EDGE_EPILOG();
}

// ---------------- mixing update (2 features/thread) ----------------
__global__ __launch_bounds__(64)
void mix_update() {
    int n = blockIdx.x, ft = threadIdx.x * 2;
    float2 dq   = *(const float2*)&g_xm[n * F3 + ft];
    float2 dmu  = *(const float2*)&g_xm[n * F3 + F_DIM + ft];
    float2 dqmu = *(const float2*)&g_xm[n * F3 + 2 * F_DIM + ft];
    float2 s = {0.f, 0.f};
    #pragma unroll
    for (int a = 0; a < 3; ++a) {
        float2 v = *(const float2*)&g_mumix[(n * 3 + a) * (2 * F_DIM) + ft];
        float2 w = *(const float2*)&g_mumix[(n * 3 + a) * (2 * F_DIM) + F_DIM + ft];
        s.x += v.x * w.x; s.y += v.y * w.y;
        float2 mv = *(const float2*)&g_mu[(n * 3 + a) * F_DIM + ft];
        float2 dv = *(const float2*)&g_dmu[(n * 3 + a) * F_DIM + ft];
        mv.x += dv.x + dmu.x * w.x;
        mv.y += dv.y + dmu.y * w.y;
        *(float2*)&g_mu[(n * 3 + a) * F_DIM + ft] = mv;
    }
    float2 qv = *(const float2*)&g_q[n * F_DIM + ft];
    qv.x += dq.x + dqmu.x * s.x;
    qv.y += dq.y + dqmu.y * s.y;
    *(float2*)&g_q[n * F_DIM + ft] = qv;
}

// ================= host launch =================
extern "C" void kernel_launch(void* const* d_in, const int* in_sizes, int n_in,
                              void* d_out, int out_size) {
    (void)in_sizes; (void)n_in; (void)out_size;
    const int*   Z       = (const int*)  d_in[0];
    const float* R       = (const float*)d_in[1];
    const int*   idx_i   = (const int*)  d_in[2];
    const int*   idx_j   = (const int*)  d_in[3];
    const float* offs    = (const float*)d_in[4];
    const float* emb     = (const float*)d_in[5];
    const float* filt_W  = (const float*)d_in[6];
    const float* filt_b  = (const float*)d_in[7];
    const float* int_W1  = (const float*)d_in[8];
    const float* int_b1  = (const float*)d_in[9];
    const float* int_W2  = (const float*)d_in[10];
    const float* int_b2  = (const float*)d_in[11];
    const float* mix_Wmu = (const float*)d_in[12];
    const float* mix_W1  = (const float*)d_in[13];
    const float* mix_b1  = (const float*)d_in[14];
    const float* mix_W2  = (const float*)d_in[15];
    const float* mix_b2  = (const float*)d_in[16];
    float* out = (float*)d_out;

    void *p_q, *p_mu, *p_x, *p_dmu, *p_mumix, *p_xm, *p_wF;
    cudaGetSymbolAddress(&p_q, g_q);
    cudaGetSymbolAddress(&p_mu, g_mu);
    cudaGetSymbolAddress(&p_x, g_x);
    cudaGetSymbolAddress(&p_dmu, g_dmu);
    cudaGetSymbolAddress(&p_mumix, g_mumix);
    cudaGetSymbolAddress(&p_xm, g_xm);
    cudaGetSymbolAddress(&p_wF, g_wF);

    cudaFuncSetAttribute(fused_mlp<0>, cudaFuncAttributeMaxDynamicSharedMemorySize, FS_TOTAL);
    cudaFuncSetAttribute(fused_mlp<2>, cudaFuncAttributeMaxDynamicSharedMemorySize, FS_TOTAL);

    fused_pre<<<NB_PRE, 384>>>(R, idx_i, idx_j, offs, filt_W, filt_b, Z, emb,
                               int_W1, int_W2, mix_Wmu, mix_W1, mix_W2);

    const __half* wF = (const __half*)p_wF;
    const int NBLK = (N_ATOMS + 63) / 64;     // 157

    for (int it = 0; it < 3; ++it) {
        size_t wb = (size_t)it * WT_PER_ITER;

        fused_mlp<0><<<NBLK, 256, FS_TOTAL>>>(
            (const float*)p_q, nullptr,
            wF + wb + 0, int_b1 + (long)it * F_DIM,
            wF + wb + 16384, int_b2 + (long)it * F3,
            (float*)p_x, N_ATOMS, F_DIM);

        if (it == 0) edge_message_csr0<<<N_ATOMS, 64>>>(idx_j);
        else         edge_message_csr <<<N_ATOMS, 64>>>(idx_j);

        if (it == 0)
            mma_gemm<0><<<dim3(4, 235), 256>>>(
                (const float*)p_dmu, nullptr, wF + wb + 65536,
                (float*)p_mumix, 3 * N_ATOMS, 2 * F_DIM, F_DIM);
        else
            mma_gemm<1><<<dim3(4, 235), 256>>>(
                (const float*)p_mu, (const float*)p_dmu, wF + wb + 65536,
                (float*)p_mumix, 3 * N_ATOMS, 2 * F_DIM, F_DIM);

        fused_mlp<2><<<NBLK, 256, FS_TOTAL>>>(
            (const float*)p_q, (const float*)p_mumix,
            wF + wb + 98304, mix_b1 + (long)it * F_DIM,
            wF + wb + 131072, mix_b2 + (long)it * F3,
            (float*)p_xm, N_ATOMS, 2 * F_DIM);

        mix_update<<<N_ATOMS, 64>>>();
    }

    cudaMemcpyAsync(out, p_q, (size_t)N_ATOMS * F_DIM * sizeof(float),
                    cudaMemcpyDeviceToDevice);
    cudaMemcpyAsync(out + (size_t)N_ATOMS * F_DIM, p_mu,
                    (size_t)N_ATOMS * 3 * F_DIM * sizeof(float),
                    cudaMemcpyDeviceToDevice);
}